// round 1
// baseline (speedup 1.0000x reference)
#include <cuda_runtime.h>
#include <math.h>

// Problem constants
#define D     128      // channels
#define KM    128      // modes
#define NTOK  8192     // grid points per batch
#define BB    16       // batch
#define TT    128      // token tile per block
#define AST   132      // padded smem stride
#define NCHUNK 16      // reduce chunks per batch
#define CH    (NTOK/NCHUNK)   // 512 tokens per reduce block
#define NTILES ((BB*NTOK)/TT) // 1024

// ---------------- scratch (static device globals; no allocation) -------------
__device__ float g_h   [BB*NTOK*D];        // activations (b,n,c)  64 MB
__device__ float g_part[BB*NCHUNK*D*KM];   // reduce partials      16 MB
__device__ float g_S   [BB*D*KM];          // S[b][c][k] = h^T B    1 MB
__device__ float g_sc  [BB*D*KM];          // score[b][kd][v] / Yt[b][k][o]
__device__ float g_c1t [KM*D*D];           // c1_w transposed (k,i,o)  8 MB
__device__ float g_c3t [KM*D*D];           // c3_w transposed (k,i,o)  8 MB
__device__ float g_colb[32*KM];            // partial column sums of B

__device__ __forceinline__ float gelu_f(float x) {
    return 0.5f * x * (1.0f + erff(x * 0.7071067811865475f));
}

// 8x8 micro-tile GEMM accumulate over smem operands.
// A layout: [k][row] stride AST ; W layout: [k][col] stride AST.
__device__ __forceinline__ void gemm8x8(const float* __restrict__ A,
                                        const float* __restrict__ W,
                                        float (&acc)[8][8], int ty, int tx, int kdim) {
    const float* ap = A + ty * 8;
    const float* wp = W + tx * 8;
#pragma unroll 4
    for (int k = 0; k < kdim; k++) {
        float4 a0 = *(const float4*)(ap + k * AST);
        float4 a1 = *(const float4*)(ap + k * AST + 4);
        float4 w0 = *(const float4*)(wp + k * AST);
        float4 w1 = *(const float4*)(wp + k * AST + 4);
        float a[8] = {a0.x, a0.y, a0.z, a0.w, a1.x, a1.y, a1.z, a1.w};
        float w[8] = {w0.x, w0.y, w0.z, w0.w, w1.x, w1.y, w1.z, w1.w};
#pragma unroll
        for (int i = 0; i < 8; i++)
#pragma unroll
            for (int j = 0; j < 8; j++)
                acc[i][j] = fmaf(a[i], w[j], acc[i][j]);
    }
}

// ---------------- small prep kernels ----------------------------------------

// partial column sums of B: g_colb[p][k] = sum_{r in chunk p} B[r][k]
__global__ void colb_kernel(const float* __restrict__ Bm) {
    int k = threadIdx.x;      // 128
    int p = blockIdx.x;       // 32 chunks of 256 rows
    float s = 0.f;
    int r0 = p * 256;
    for (int r = 0; r < 256; r++) s += Bm[(r0 + r) * KM + k];
    g_colb[p * KM + k] = s;
}

// transpose conv weight (i,o,k) -> (k,i,o).  Treat input as (16384 rows io, 128 cols k).
__global__ void transpose_w_kernel(const float* __restrict__ W, int which) {
    float* Wt = which ? g_c3t : g_c1t;
    __shared__ float tile[32][33];
    int x0 = blockIdx.x * 32;   // io
    int y0 = blockIdx.y * 32;   // k
    int tx = threadIdx.x, ty = threadIdx.y;  // 32 x 8
#pragma unroll
    for (int r = 0; r < 32; r += 8)
        tile[ty + r][tx] = W[(x0 + ty + r) * KM + y0 + tx];
    __syncthreads();
#pragma unroll
    for (int r = 0; r < 32; r += 8)
        Wt[(y0 + ty + r) * (D * D) + x0 + tx] = tile[tx][ty + r];
}

// ---------------- fc0: h = gelu(x@w1+b1)@w2 + b2 ----------------------------
__global__ void fc0_kernel(const float* __restrict__ x,  const float* __restrict__ w1,
                           const float* __restrict__ b1, const float* __restrict__ w2,
                           const float* __restrict__ b2) {
    extern __shared__ float sm[];
    float* As  = sm;                 // [c][t]
    float* Ws  = sm + D * AST;       // [c][o]
    float* xs  = Ws + D * AST;       // 256
    float* w1s = xs + 2 * TT;        // 256
    float* b1s = w1s + 2 * D;        // 128
    int tid = threadIdx.x;
    int tok0 = blockIdx.x * TT;

    xs[tid] = x[tok0 * 2 + tid];
    if (tid < 256) w1s[tid] = w1[tid];
    if (tid < 128) b1s[tid] = b1[tid];
    __syncthreads();

    for (int idx = tid; idx < TT * D; idx += 256) {
        int t = idx >> 7, c = idx & 127;
        float v = xs[t * 2] * w1s[c] + xs[t * 2 + 1] * w1s[D + c] + b1s[c];
        As[c * AST + t] = gelu_f(v);
    }
    for (int idx = tid; idx < D * D; idx += 256)
        Ws[(idx >> 7) * AST + (idx & 127)] = w2[idx];
    __syncthreads();

    int ty = tid >> 4, tx = tid & 15;
    float acc[8][8] = {};
    gemm8x8(As, Ws, acc, ty, tx, D);

#pragma unroll
    for (int i = 0; i < 8; i++) {
        int row = (tok0 + ty * 8 + i) * D + tx * 8;
        float4 o0 = make_float4(acc[i][0] + b2[tx * 8 + 0], acc[i][1] + b2[tx * 8 + 1],
                                acc[i][2] + b2[tx * 8 + 2], acc[i][3] + b2[tx * 8 + 3]);
        float4 o1 = make_float4(acc[i][4] + b2[tx * 8 + 4], acc[i][5] + b2[tx * 8 + 5],
                                acc[i][6] + b2[tx * 8 + 6], acc[i][7] + b2[tx * 8 + 7]);
        *(float4*)&g_h[row]     = o0;
        *(float4*)&g_h[row + 4] = o1;
    }
}

// ---------------- reduce: part[b][cz][c][k] = sum_n h[b][n][c] B[n][k] ------
__global__ void reduce_kernel(const float* __restrict__ Bm) {
    __shared__ float hs[32 * AST];
    __shared__ float bs[32 * AST];
    int cz = blockIdx.x, b = blockIdx.y;
    int tid = threadIdx.x, ty = tid >> 4, tx = tid & 15;
    float acc[8][8] = {};
    int hbase = (b * NTOK + cz * CH) * D;
    int bbase = (cz * CH) * KM;
    for (int n0 = 0; n0 < CH; n0 += 32) {
        for (int idx = tid; idx < 32 * D; idx += 256) {
            int n = idx >> 7, c = idx & 127;
            hs[n * AST + c] = g_h[hbase + (n0 + n) * D + c];
            bs[n * AST + c] = Bm[bbase + (n0 + n) * KM + c];
        }
        __syncthreads();
        gemm8x8(hs, bs, acc, ty, tx, 32);
        __syncthreads();
    }
    int obase = (b * NCHUNK + cz) * D * KM;
#pragma unroll
    for (int i = 0; i < 8; i++) {
        int row = obase + (ty * 8 + i) * KM + tx * 8;
        *(float4*)&g_part[row]     = make_float4(acc[i][0], acc[i][1], acc[i][2], acc[i][3]);
        *(float4*)&g_part[row + 4] = make_float4(acc[i][4], acc[i][5], acc[i][6], acc[i][7]);
    }
}

__global__ void reduce2_kernel() {
    int e = blockIdx.x * 256 + threadIdx.x;   // 64 * 256 = 16384
    int b = blockIdx.y;
    float s = 0.f;
#pragma unroll
    for (int cz = 0; cz < NCHUNK; cz++)
        s += g_part[(b * NCHUNK + cz) * D * KM + e];
    g_S[b * D * KM + e] = s;
}

// ---------------- attention score: score = wk^T S + bk (x) colB -------------
__global__ void score_kernel(const float* __restrict__ wk, const float* __restrict__ bk) {
    extern __shared__ float sm[];
    float* As = sm;               // [c][kd]
    float* Ws = sm + D * AST;     // [c][v]
    float* cb = Ws + D * AST;     // 128
    int b = blockIdx.x, tid = threadIdx.x;
    if (tid < KM) {
        float s = 0.f;
        for (int p = 0; p < 32; p++) s += g_colb[p * KM + tid];
        cb[tid] = s;
    }
    for (int idx = tid; idx < D * D; idx += 256) {
        As[(idx >> 7) * AST + (idx & 127)] = wk[idx];
        Ws[(idx >> 7) * AST + (idx & 127)] = g_S[b * D * KM + idx];
    }
    __syncthreads();
    int ty = tid >> 4, tx = tid & 15;
    float acc[8][8] = {};
    gemm8x8(As, Ws, acc, ty, tx, D);
#pragma unroll
    for (int i = 0; i < 8; i++) {
        float bkk = bk[ty * 8 + i];
        int row = (b * D + ty * 8 + i) * KM + tx * 8;
#pragma unroll
        for (int j = 0; j < 8; j++)
            g_sc[row + j] = acc[i][j] + bkk * cb[tx * 8 + j];
    }
}

// ---------------- per-mode conv: Yt[b][k][o] = sum_i S[b][i][k] W[k][i][o] --
__global__ void gconv_modes_kernel(int which) {
    const float* Wt = which ? g_c3t : g_c1t;
    __shared__ float Ss[BB * D];
    int k = blockIdx.x, tid = threadIdx.x;
    for (int idx = tid; idx < BB * D; idx += 256) {
        int b = idx >> 7, i = idx & 127;
        Ss[idx] = g_S[(b * D + i) * KM + k];
    }
    __syncthreads();
    int hi = tid >> 7, o = tid & 127;
    float acc[8] = {};
    for (int i = 0; i < D; i++) {
        float w = Wt[(k * D + i) * D + o];
#pragma unroll
        for (int q = 0; q < 8; q++)
            acc[q] = fmaf(Ss[(hi * 8 + q) * D + i], w, acc[q]);
    }
#pragma unroll
    for (int q = 0; q < 8; q++)
        g_sc[((hi * 8 + q) * KM + k) * D + o] = acc[q];
}

// ---------------- attention map: attn + residual + FFN, in-place on h -------
__global__ void attn_map_kernel(const float* __restrict__ Bm,  const float* __restrict__ f1w,
                                const float* __restrict__ f1b, const float* __restrict__ f2w,
                                const float* __restrict__ f2b) {
    extern __shared__ float sm[];
    float* As = sm;                // phase1: B^T tile ; phase2: xt^T
    float* Ws = As + D * AST;      // score / f1w / f2w
    float* Gs = Ws + D * AST;      // gelu(hidden)^T
    int tid = threadIdx.x, ty = tid >> 4, tx = tid & 15;
    int b = blockIdx.x >> 6;
    int n0 = (blockIdx.x & 63) * TT;
    int tok0 = b * NTOK + n0;

    for (int idx = tid; idx < TT * KM; idx += 256) {
        int t = idx >> 7, kd = idx & 127;
        As[kd * AST + t] = Bm[(n0 + t) * KM + kd];
    }
    for (int idx = tid; idx < D * KM; idx += 256)
        Ws[(idx >> 7) * AST + (idx & 127)] = g_sc[b * D * KM + idx];
    __syncthreads();

    float acc[8][8] = {};
    gemm8x8(As, Ws, acc, ty, tx, KM);       // attn[t][v]
    __syncthreads();                        // all reads of As/Ws done

    // xt = gelu(attn) + h ; write to global h (in-place) and As transposed
#pragma unroll
    for (int i = 0; i < 8; i++) {
        int row = (tok0 + ty * 8 + i) * D + tx * 8;
        float4 h0 = *(const float4*)&g_h[row];
        float4 h1 = *(const float4*)&g_h[row + 4];
        float xt[8];
        xt[0] = gelu_f(acc[i][0]) + h0.x;  xt[1] = gelu_f(acc[i][1]) + h0.y;
        xt[2] = gelu_f(acc[i][2]) + h0.z;  xt[3] = gelu_f(acc[i][3]) + h0.w;
        xt[4] = gelu_f(acc[i][4]) + h1.x;  xt[5] = gelu_f(acc[i][5]) + h1.y;
        xt[6] = gelu_f(acc[i][6]) + h1.z;  xt[7] = gelu_f(acc[i][7]) + h1.w;
        *(float4*)&g_h[row]     = make_float4(xt[0], xt[1], xt[2], xt[3]);
        *(float4*)&g_h[row + 4] = make_float4(xt[4], xt[5], xt[6], xt[7]);
#pragma unroll
        for (int j = 0; j < 8; j++)
            As[(tx * 8 + j) * AST + ty * 8 + i] = xt[j];
    }
    for (int idx = tid; idx < D * D; idx += 256)
        Ws[(idx >> 7) * AST + (idx & 127)] = f1w[idx];
    __syncthreads();

    float acc2[8][8] = {};
    gemm8x8(As, Ws, acc2, ty, tx, D);       // u = xt @ f1w
#pragma unroll
    for (int i = 0; i < 8; i++)
#pragma unroll
        for (int j = 0; j < 8; j++)
            Gs[(tx * 8 + j) * AST + ty * 8 + i] = gelu_f(acc2[i][j] + f1b[tx * 8 + j]);
    __syncthreads();                        // reads of Ws done, Gs complete
    for (int idx = tid; idx < D * D; idx += 256)
        Ws[(idx >> 7) * AST + (idx & 127)] = f2w[idx];
    __syncthreads();

    float acc3[8][8] = {};
    gemm8x8(Gs, Ws, acc3, ty, tx, D);       // r = g @ f2w
#pragma unroll
    for (int i = 0; i < 8; i++) {
        int row = (tok0 + ty * 8 + i) * D + tx * 8;
        float4 h0 = *(const float4*)&g_h[row];     // xt written above (same thread)
        float4 h1 = *(const float4*)&g_h[row + 4];
        float4 o0 = make_float4(h0.x + acc3[i][0] + f2b[tx * 8 + 0],
                                h0.y + acc3[i][1] + f2b[tx * 8 + 1],
                                h0.z + acc3[i][2] + f2b[tx * 8 + 2],
                                h0.w + acc3[i][3] + f2b[tx * 8 + 3]);
        float4 o1 = make_float4(h1.x + acc3[i][4] + f2b[tx * 8 + 4],
                                h1.y + acc3[i][5] + f2b[tx * 8 + 5],
                                h1.z + acc3[i][6] + f2b[tx * 8 + 6],
                                h1.w + acc3[i][7] + f2b[tx * 8 + 7]);
        *(float4*)&g_h[row]     = o0;
        *(float4*)&g_h[row + 4] = o1;
    }
}

// ---------------- gconv map: h += act(B@Yt + h@W + b), in-place -------------
__global__ void gconv_map_kernel(const float* __restrict__ Bm, const float* __restrict__ ww,
                                 const float* __restrict__ wb, int act) {
    extern __shared__ float sm[];
    float* As = sm;
    float* Ws = As + D * AST;
    int tid = threadIdx.x, ty = tid >> 4, tx = tid & 15;
    int b = blockIdx.x >> 6;
    int n0 = (blockIdx.x & 63) * TT;
    int tok0 = b * NTOK + n0;

    // phase 1: x1 = B_tile @ Yt
    for (int idx = tid; idx < TT * KM; idx += 256) {
        int t = idx >> 7, kd = idx & 127;
        As[kd * AST + t] = Bm[(n0 + t) * KM + kd];
    }
    for (int idx = tid; idx < D * KM; idx += 256)
        Ws[(idx >> 7) * AST + (idx & 127)] = g_sc[b * D * KM + idx];  // Yt[k][o]
    __syncthreads();

    float acc[8][8] = {};
    gemm8x8(As, Ws, acc, ty, tx, KM);
    __syncthreads();

    // phase 2: accumulate x2 = h @ W into the same accumulators
    for (int idx = tid; idx < TT * D; idx += 256) {
        int t = idx >> 7, c = idx & 127;
        As[c * AST + t] = g_h[(tok0 + t) * D + c];
    }
    for (int idx = tid; idx < D * D; idx += 256)
        Ws[(idx >> 7) * AST + (idx & 127)] = ww[idx];
    __syncthreads();
    gemm8x8(As, Ws, acc, ty, tx, D);

#pragma unroll
    for (int i = 0; i < 8; i++) {
        int row = (tok0 + ty * 8 + i) * D + tx * 8;
        float4 h0 = *(const float4*)&g_h[row];
        float4 h1 = *(const float4*)&g_h[row + 4];
        float z[8];
#pragma unroll
        for (int j = 0; j < 8; j++) {
            float zz = acc[i][j] + wb[tx * 8 + j];
            z[j] = act ? gelu_f(zz) : zz;
        }
        *(float4*)&g_h[row]     = make_float4(h0.x + z[0], h0.y + z[1], h0.z + z[2], h0.w + z[3]);
        *(float4*)&g_h[row + 4] = make_float4(h1.x + z[4], h1.y + z[5], h1.z + z[6], h1.w + z[7]);
    }
}

// ---------------- head: out = gelu(h@fc1+b1) @ fc2 + b2 ---------------------
__global__ void head_kernel(const float* __restrict__ fc1w, const float* __restrict__ fc1b,
                            const float* __restrict__ fc2w, const float* __restrict__ fc2b,
                            float* __restrict__ out) {
    extern __shared__ float sm[];
    float* As = sm;
    float* Ws = As + D * AST;
    int tid = threadIdx.x, ty = tid >> 4, tx = tid & 15;
    int b = blockIdx.x >> 6;
    int n0 = (blockIdx.x & 63) * TT;
    int tok0 = b * NTOK + n0;

    for (int idx = tid; idx < TT * D; idx += 256) {
        int t = idx >> 7, c = idx & 127;
        As[c * AST + t] = g_h[(tok0 + t) * D + c];
    }
    for (int idx = tid; idx < D * D; idx += 256)
        Ws[(idx >> 7) * AST + (idx & 127)] = fc1w[idx];
    __syncthreads();

    float acc[8][8] = {};
    gemm8x8(As, Ws, acc, ty, tx, D);

    float fb[8], fw[8];
#pragma unroll
    for (int j = 0; j < 8; j++) { fb[j] = fc1b[tx * 8 + j]; fw[j] = fc2w[tx * 8 + j]; }
    float p[8];
#pragma unroll
    for (int i = 0; i < 8; i++) {
        float s = 0.f;
#pragma unroll
        for (int j = 0; j < 8; j++)
            s = fmaf(gelu_f(acc[i][j] + fb[j]), fw[j], s);
        p[i] = s;
    }
    __syncthreads();            // all gemm reads of Ws done
    float* Rs = Ws;             // reuse as reduction scratch [t][16]
#pragma unroll
    for (int i = 0; i < 8; i++)
        Rs[(ty * 8 + i) * 16 + tx] = p[i];
    __syncthreads();
    if (tid < TT) {
        float s = 0.f;
#pragma unroll
        for (int q = 0; q < 16; q++) s += Rs[tid * 16 + q];
        out[tok0 + tid] = s + fc2b[0];
    }
}

// ---------------- launch ----------------------------------------------------
extern "C" void kernel_launch(void* const* d_in, const int* in_sizes, int n_in,
                              void* d_out, int out_size) {
    const float* x      = (const float*)d_in[0];
    const float* Bm     = (const float*)d_in[1];
    const float* fc0_w1 = (const float*)d_in[2];
    const float* fc0_b1 = (const float*)d_in[3];
    const float* fc0_w2 = (const float*)d_in[4];
    const float* fc0_b2 = (const float*)d_in[5];
    const float* a0_wk  = (const float*)d_in[6];
    const float* a0_bk  = (const float*)d_in[7];
    const float* a0_f1w = (const float*)d_in[8];
    const float* a0_f1b = (const float*)d_in[9];
    const float* a0_f2w = (const float*)d_in[10];
    const float* a0_f2b = (const float*)d_in[11];
    const float* c1_w   = (const float*)d_in[12];
    const float* w1_w   = (const float*)d_in[13];
    const float* w1_b   = (const float*)d_in[14];
    const float* a2_wk  = (const float*)d_in[15];
    const float* a2_bk  = (const float*)d_in[16];
    const float* a2_f1w = (const float*)d_in[17];
    const float* a2_f1b = (const float*)d_in[18];
    const float* a2_f2w = (const float*)d_in[19];
    const float* a2_f2b = (const float*)d_in[20];
    const float* c3_w   = (const float*)d_in[21];
    const float* w3_w   = (const float*)d_in[22];
    const float* w3_b   = (const float*)d_in[23];
    const float* fc1_w  = (const float*)d_in[24];
    const float* fc1_b  = (const float*)d_in[25];
    const float* fc2_w  = (const float*)d_in[26];
    const float* fc2_b  = (const float*)d_in[27];
    float* out = (float*)d_out;

    const size_t SM2 = (size_t)(2 * D * AST + 1024) * sizeof(float);  // ~139 KB
    const size_t SM3 = (size_t)(3 * D * AST) * sizeof(float);         // ~198 KB
    cudaFuncSetAttribute((const void*)fc0_kernel,       cudaFuncAttributeMaxDynamicSharedMemorySize, (int)SM2);
    cudaFuncSetAttribute((const void*)score_kernel,     cudaFuncAttributeMaxDynamicSharedMemorySize, (int)SM2);
    cudaFuncSetAttribute((const void*)attn_map_kernel,  cudaFuncAttributeMaxDynamicSharedMemorySize, (int)SM3);
    cudaFuncSetAttribute((const void*)gconv_map_kernel, cudaFuncAttributeMaxDynamicSharedMemorySize, (int)SM2);
    cudaFuncSetAttribute((const void*)head_kernel,      cudaFuncAttributeMaxDynamicSharedMemorySize, (int)SM2);

    colb_kernel<<<32, 128>>>(Bm);
    transpose_w_kernel<<<dim3(512, 4), dim3(32, 8)>>>(c1_w, 0);
    transpose_w_kernel<<<dim3(512, 4), dim3(32, 8)>>>(c3_w, 1);

    fc0_kernel<<<NTILES, 256, SM2>>>(x, fc0_w1, fc0_b1, fc0_w2, fc0_b2);

    // layer 0: DoubleAttention
    reduce_kernel<<<dim3(NCHUNK, BB), 256>>>(Bm);
    reduce2_kernel<<<dim3(64, BB), 256>>>();
    score_kernel<<<BB, 256, SM2>>>(a0_wk, a0_bk);
    attn_map_kernel<<<NTILES, 256, SM3>>>(Bm, a0_f1w, a0_f1b, a0_f2w, a0_f2b);

    // layer 1: GalerkinConv + pointwise conv, gelu, residual
    reduce_kernel<<<dim3(NCHUNK, BB), 256>>>(Bm);
    reduce2_kernel<<<dim3(64, BB), 256>>>();
    gconv_modes_kernel<<<KM, 256>>>(0);
    gconv_map_kernel<<<NTILES, 256, SM2>>>(Bm, w1_w, w1_b, 1);

    // layer 2: DoubleAttention
    reduce_kernel<<<dim3(NCHUNK, BB), 256>>>(Bm);
    reduce2_kernel<<<dim3(64, BB), 256>>>();
    score_kernel<<<BB, 256, SM2>>>(a2_wk, a2_bk);
    attn_map_kernel<<<NTILES, 256, SM3>>>(Bm, a2_f1w, a2_f1b, a2_f2w, a2_f2b);

    // layer 3: GalerkinConv + pointwise conv, no act, residual
    reduce_kernel<<<dim3(NCHUNK, BB), 256>>>(Bm);
    reduce2_kernel<<<dim3(64, BB), 256>>>();
    gconv_modes_kernel<<<KM, 256>>>(1);
    gconv_map_kernel<<<NTILES, 256, SM2>>>(Bm, w3_w, w3_b, 0);

    head_kernel<<<NTILES, 256, SM2>>>(fc1_w, fc1_b, fc2_w, fc2_b, out);
}

// round 4
// speedup vs baseline: 1.6136x; 1.6136x over previous
#include <cuda_runtime.h>
#include <cuda_bf16.h>
#include <math.h>
#include <cstdint>

#define D     128
#define KM    128
#define NTOK  8192
#define BB    16
#define NCHUNK 16
#define NTILES ((BB*NTOK)/128)   // 1024
#define XST   129                // padded fp32 stage stride

// smem tile: 128 rows x 128 bf16 cols, 256 B/row, swizzled
#define TILEB 32768
#define OFF_AHI 0
#define OFF_ALO TILEB
#define OFF_BHI (2*TILEB)
#define OFF_BLO (3*TILEB)
#define OFF_CTRL (4*TILEB)            // 131072, 4 KB ctrl
#define OFF_X    (OFF_CTRL + 4096)    // fp32 stage 128*129*4 = 66048
#define SM_MID   OFF_X                // 135168
#define SM_BIG   (OFF_X + 66048)      // 201216

// ---------------- scratch ----------------------------------------------------
__device__ float g_h   [BB*NTOK*D];
__device__ float g_part[BB*NCHUNK*D*KM];
__device__ float g_S   [BB*D*KM];
__device__ float g_sc  [BB*D*KM];          // score^T [b][v][kd]  /  Yt^T [b][o][k]
__device__ float g_c1t [KM*D*D];
__device__ float g_c3t [KM*D*D];
__device__ float g_colb[32*KM];

// ---------------- helpers ----------------------------------------------------
__device__ __forceinline__ uint32_t smem_u32(const void* p) {
    uint32_t a;
    asm("{ .reg .u64 t; cvta.to.shared.u64 t, %1; cvt.u32.u64 %0, t; }" : "=r"(a) : "l"(p));
    return a;
}
__device__ __forceinline__ float gelu_f(float x) {
    return 0.5f * x * (1.0f + erff(x * 0.7071067811865475f));
}
// swizzled byte addr of tile element (row r, col c) ; c even for u32 stores
__device__ __forceinline__ uint32_t taddr(int r, int c) {
    return (uint32_t)(r * 256 + ((c << 1) ^ ((r & 7) << 4)));
}
__device__ __forceinline__ uint32_t split_pack(float x0, float x1, uint32_t& lop) {
    __nv_bfloat16 h0 = __float2bfloat16(x0);
    __nv_bfloat16 h1 = __float2bfloat16(x1);
    __nv_bfloat16 l0 = __float2bfloat16(x0 - __bfloat162float(h0));
    __nv_bfloat16 l1 = __float2bfloat16(x1 - __bfloat162float(h1));
    __nv_bfloat162 hp; hp.x = h0; hp.y = h1;
    __nv_bfloat162 lp; lp.x = l0; lp.y = l1;
    lop = *(uint32_t*)&lp;
    return *(uint32_t*)&hp;
}

__device__ __forceinline__ void ldsm4(uint32_t a[4], uint32_t addr) {
    asm volatile("ldmatrix.sync.aligned.m8n8.x4.shared.b16 {%0,%1,%2,%3}, [%4];"
        : "=r"(a[0]), "=r"(a[1]), "=r"(a[2]), "=r"(a[3]) : "r"(addr));
}
__device__ __forceinline__ void ldsm2(uint32_t b[2], uint32_t addr) {
    asm volatile("ldmatrix.sync.aligned.m8n8.x2.shared.b16 {%0,%1}, [%2];"
        : "=r"(b[0]), "=r"(b[1]) : "r"(addr));
}
__device__ __forceinline__ void mma16816(float c[4], const uint32_t a[4], const uint32_t b[2]) {
    asm volatile("mma.sync.aligned.m16n8k16.row.col.f32.bf16.bf16.f32 "
        "{%0,%1,%2,%3}, {%4,%5,%6,%7}, {%8,%9}, {%0,%1,%2,%3};"
        : "+f"(c[0]), "+f"(c[1]), "+f"(c[2]), "+f"(c[3])
        : "r"(a[0]), "r"(a[1]), "r"(a[2]), "r"(a[3]), "r"(b[0]), "r"(b[1]));
}

// C[t][o] += A[t][k] * B[o][k] with 3-pass hi/lo split. acc[2][8][4].
// warp tile: rows m0..m0+31 (2 m-subtiles of 16), cols n0..n0+63 (8 n-subtiles of 8)
__device__ __forceinline__ void gemm_split(uint32_t sAhi, uint32_t sAlo,
                                           uint32_t sBhi, uint32_t sBlo,
                                           float acc[2][8][4], int lane, int m0, int n0) {
#pragma unroll
    for (int k0 = 0; k0 < 128; k0 += 16) {
        uint32_t aoff = taddr(m0 + (lane & 15), k0 + ((lane >> 4) << 3));
        uint32_t aoff2 = taddr(m0 + 16 + (lane & 15), k0 + ((lane >> 4) << 3));
        uint32_t ah0[4], ah1[4], al0[4], al1[4];
        ldsm4(ah0, sAhi + aoff);
        ldsm4(ah1, sAhi + aoff2);
        ldsm4(al0, sAlo + aoff);
        ldsm4(al1, sAlo + aoff2);
#pragma unroll
        for (int j = 0; j < 8; j++) {
            uint32_t boff = taddr(n0 + j * 8 + (lane & 7), k0 + ((lane >> 3) & 1) * 8);
            uint32_t bh[2], bl[2];
            ldsm2(bh, sBhi + boff);
            ldsm2(bl, sBlo + boff);
            mma16816(acc[0][j], ah0, bh);
            mma16816(acc[1][j], ah1, bh);
            mma16816(acc[0][j], ah0, bl);
            mma16816(acc[1][j], ah1, bl);
            mma16816(acc[0][j], al0, bh);
            mma16816(acc[1][j], al1, bh);
        }
    }
}

// tile[r][c] = G[r*ldg + c]
__device__ __forceinline__ void load_direct(char* hi, char* lo, const float* __restrict__ G,
                                            int ldg, int tid) {
    for (int p = tid; p < 128 * 64; p += 256) {
        int r = p >> 6, c = (p & 63) << 1;
        float2 v = *(const float2*)(G + r * ldg + c);
        uint32_t lw, hw = split_pack(v.x, v.y, lw);
        uint32_t a = taddr(r, c);
        *(uint32_t*)(hi + a) = hw; *(uint32_t*)(lo + a) = lw;
    }
}
// tile[r][c] = G[c*ldg + r]
__device__ __forceinline__ void load_trans(char* hi, char* lo, const float* __restrict__ G,
                                           int ldg, int tid) {
    for (int p = tid; p < 128 * 64; p += 256) {
        int r = p & 127, c = (p >> 7) << 1;
        float v0 = G[c * ldg + r], v1 = G[(c + 1) * ldg + r];
        uint32_t lw, hw = split_pack(v0, v1, lw);
        uint32_t a = taddr(r, c);
        *(uint32_t*)(hi + a) = hw; *(uint32_t*)(lo + a) = lw;
    }
}

#define WARP_SETUP()                                                 \
    int tid = threadIdx.x;                                           \
    int lane = tid & 31, wid = tid >> 5;                             \
    int m0 = (wid & 3) * 32, n0 = (wid >> 2) * 64;                   \
    int qr = lane >> 2, qc = (lane & 3) * 2;                         \
    (void)qr; (void)qc;

#define TILE_PTRS()                                                  \
    extern __shared__ __align__(1024) char dsm[];                    \
    char* Ahi = dsm + OFF_AHI; char* Alo = dsm + OFF_ALO;            \
    char* Bhi = dsm + OFF_BHI; char* Blo = dsm + OFF_BLO;            \
    uint32_t sb = smem_u32(dsm);                                     \
    uint32_t sAhi = sb + OFF_AHI, sAlo = sb + OFF_ALO;               \
    uint32_t sBhi = sb + OFF_BHI, sBlo = sb + OFF_BLO;               \
    float* ctrl = (float*)(dsm + OFF_CTRL);                          \
    (void)ctrl;

// ---------------- small prep kernels ----------------------------------------
__global__ void colb_kernel(const float* __restrict__ Bm) {
    int k = threadIdx.x, p = blockIdx.x;
    float s = 0.f;
    int r0 = p * 256;
    for (int r = 0; r < 256; r++) s += Bm[(r0 + r) * KM + k];
    g_colb[p * KM + k] = s;
}

__global__ void transpose_w_kernel(const float* __restrict__ W, int which) {
    float* Wt = which ? g_c3t : g_c1t;
    __shared__ float tile[32][33];
    int x0 = blockIdx.x * 32, y0 = blockIdx.y * 32;
    int tx = threadIdx.x, ty = threadIdx.y;
#pragma unroll
    for (int r = 0; r < 32; r += 8)
        tile[ty + r][tx] = W[(x0 + ty + r) * KM + y0 + tx];
    __syncthreads();
#pragma unroll
    for (int r = 0; r < 32; r += 8)
        Wt[(y0 + ty + r) * (D * D) + x0 + tx] = tile[tx][ty + r];
}

__global__ void reduce2_kernel() {
    int e = blockIdx.x * 256 + threadIdx.x;
    int b = blockIdx.y;
    float s = 0.f;
#pragma unroll
    for (int cz = 0; cz < NCHUNK; cz++)
        s += g_part[(b * NCHUNK + cz) * D * KM + e];
    g_S[b * D * KM + e] = s;
}

#define AST 132
__device__ __forceinline__ void gemm8x8(const float* __restrict__ A, const float* __restrict__ W,
                                        float (&acc)[8][8], int ty, int tx, int kdim) {
    const float* ap = A + ty * 8;
    const float* wp = W + tx * 8;
#pragma unroll 4
    for (int k = 0; k < kdim; k++) {
        float4 a0 = *(const float4*)(ap + k * AST);
        float4 a1 = *(const float4*)(ap + k * AST + 4);
        float4 w0 = *(const float4*)(wp + k * AST);
        float4 w1 = *(const float4*)(wp + k * AST + 4);
        float a[8] = {a0.x,a0.y,a0.z,a0.w,a1.x,a1.y,a1.z,a1.w};
        float w[8] = {w0.x,w0.y,w0.z,w0.w,w1.x,w1.y,w1.z,w1.w};
#pragma unroll
        for (int i = 0; i < 8; i++)
#pragma unroll
            for (int j = 0; j < 8; j++)
                acc[i][j] = fmaf(a[i], w[j], acc[i][j]);
    }
}

// score^T[b][v][kd] = sum_c wk[c][kd] S[c][v] + bk[kd]*colB[v]
__global__ void score_kernel(const float* __restrict__ wk, const float* __restrict__ bk) {
    extern __shared__ float sm[];
    float* As = sm;
    float* Ws = sm + D * AST;
    float* cb = Ws + D * AST;
    int b = blockIdx.x, tid = threadIdx.x;
    if (tid < KM) {
        float s = 0.f;
        for (int p = 0; p < 32; p++) s += g_colb[p * KM + tid];
        cb[tid] = s;
    }
    for (int idx = tid; idx < D * D; idx += 256) {
        As[(idx >> 7) * AST + (idx & 127)] = wk[idx];
        Ws[(idx >> 7) * AST + (idx & 127)] = g_S[b * D * KM + idx];
    }
    __syncthreads();
    int ty = tid >> 4, tx = tid & 15;
    float acc[8][8] = {};
    gemm8x8(As, Ws, acc, ty, tx, D);
#pragma unroll
    for (int i = 0; i < 8; i++) {
        float bkk = bk[ty * 8 + i];
#pragma unroll
        for (int j = 0; j < 8; j++)
            g_sc[(b * D + tx * 8 + j) * KM + ty * 8 + i] = acc[i][j] + bkk * cb[tx * 8 + j];
    }
}

// Yt^T[b][o][k] = sum_i S[b][i][k] W[k][i][o]
__global__ void gconv_modes_kernel(int which) {
    const float* Wt = which ? g_c3t : g_c1t;
    __shared__ float Ss[BB * D];
    int k = blockIdx.x, tid = threadIdx.x;
    for (int idx = tid; idx < BB * D; idx += 256)
        Ss[idx] = g_S[((idx >> 7) * D + (idx & 127)) * KM + k];
    __syncthreads();
    int hi = tid >> 7, o = tid & 127;
    float acc[8] = {};
    for (int i = 0; i < D; i++) {
        float w = Wt[(k * D + i) * D + o];
#pragma unroll
        for (int q = 0; q < 8; q++)
            acc[q] = fmaf(Ss[(hi * 8 + q) * D + i], w, acc[q]);
    }
#pragma unroll
    for (int q = 0; q < 8; q++)
        g_sc[((hi * 8 + q) * D + o) * KM + k] = acc[q];
}

// ---------------- fc0 ---------------------------------------------------------
__global__ __launch_bounds__(256, 1)
void fc0_kernel(const float* __restrict__ x, const float* __restrict__ w1,
                const float* __restrict__ b1, const float* __restrict__ w2,
                const float* __restrict__ b2) {
    TILE_PTRS(); WARP_SETUP();
    float* xs  = ctrl;          // 256
    float* w1s = ctrl + 256;    // 256
    float* b1s = ctrl + 512;    // 128
    float* b2s = ctrl + 640;    // 128
    int tok0 = blockIdx.x * 128;

    xs[tid] = x[tok0 * 2 + tid];
    if (tid < 256) w1s[tid] = w1[tid];
    if (tid < 128) { b1s[tid] = b1[tid]; b2s[tid] = b2[tid]; }
    __syncthreads();

    for (int p = tid; p < 128 * 64; p += 256) {
        int r = p >> 6, c = (p & 63) << 1;
        float v0 = gelu_f(xs[2*r] * w1s[c]   + xs[2*r+1] * w1s[128+c]   + b1s[c]);
        float v1 = gelu_f(xs[2*r] * w1s[c+1] + xs[2*r+1] * w1s[128+c+1] + b1s[c+1]);
        uint32_t lw, hw = split_pack(v0, v1, lw);
        uint32_t a = taddr(r, c);
        *(uint32_t*)(Ahi + a) = hw; *(uint32_t*)(Alo + a) = lw;
    }
    load_trans(Bhi, Blo, w2, D, tid);     // B[o][c] = w2[c][o]
    __syncthreads();

    float acc[2][8][4] = {};
    gemm_split(sAhi, sAlo, sBhi, sBlo, acc, lane, m0, n0);

#pragma unroll
    for (int mt = 0; mt < 2; mt++)
#pragma unroll
        for (int j = 0; j < 8; j++) {
            int row = m0 + mt * 16 + qr, col = n0 + j * 8 + qc;
            *(float2*)&g_h[(size_t)(tok0 + row) * D + col] =
                make_float2(acc[mt][j][0] + b2s[col], acc[mt][j][1] + b2s[col + 1]);
            *(float2*)&g_h[(size_t)(tok0 + row + 8) * D + col] =
                make_float2(acc[mt][j][2] + b2s[col], acc[mt][j][3] + b2s[col + 1]);
        }
}

// ---------------- reduce: part[c][k] = sum_t h[t][c] B[t][k] (512-token chunk)
__global__ __launch_bounds__(256, 1)
void reduce_kernel(const float* __restrict__ Bm) {
    TILE_PTRS(); WARP_SETUP();
    int cz = blockIdx.x, b = blockIdx.y;
    float acc[2][8][4] = {};
    for (int sub = 0; sub < 4; sub++) {
        int nb = cz * 512 + sub * 128;
        load_trans(Ahi, Alo, g_h + (size_t)(b * NTOK + nb) * D, D, tid);  // [c][t]
        load_trans(Bhi, Blo, Bm + (size_t)nb * KM, KM, tid);              // [k][t]
        __syncthreads();
        gemm_split(sAhi, sAlo, sBhi, sBlo, acc, lane, m0, n0);
        __syncthreads();
    }
    size_t ob = (size_t)(b * NCHUNK + cz) * D * KM;
#pragma unroll
    for (int mt = 0; mt < 2; mt++)
#pragma unroll
        for (int j = 0; j < 8; j++) {
            int row = m0 + mt * 16 + qr, col = n0 + j * 8 + qc;
            *(float2*)&g_part[ob + (size_t)row * KM + col] = make_float2(acc[mt][j][0], acc[mt][j][1]);
            *(float2*)&g_part[ob + (size_t)(row + 8) * KM + col] = make_float2(acc[mt][j][2], acc[mt][j][3]);
        }
}

// ---------------- attention map (3 chained GEMMs, reg accumulators) ----------
__global__ __launch_bounds__(256, 1)
void attn_map_kernel(const float* __restrict__ Bm,  const float* __restrict__ f1w,
                     const float* __restrict__ f1b, const float* __restrict__ f2w,
                     const float* __restrict__ f2b) {
    TILE_PTRS(); WARP_SETUP();
    float* Xs = (float*)(dsm + OFF_X);
    int b = blockIdx.x >> 6;
    int n0t = (blockIdx.x & 63) * 128;
    size_t tok0 = (size_t)b * NTOK + n0t;

    if (tid < 128) { ctrl[tid] = f1b[tid]; ctrl[128 + tid] = f2b[tid]; }
    load_direct(Ahi, Alo, Bm + (size_t)n0t * KM, KM, tid);       // [t][kd]
    load_direct(Bhi, Blo, g_sc + (size_t)b * D * KM, KM, tid);   // [v][kd]
    for (int idx = tid; idx < 128 * 128; idx += 256)
        Xs[(idx >> 7) * XST + (idx & 127)] = g_h[(tok0 + (idx >> 7)) * D + (idx & 127)];
    __syncthreads();

    float acc[2][8][4] = {};
    gemm_split(sAhi, sAlo, sBhi, sBlo, acc, lane, m0, n0);   // attn
    __syncthreads();

    // ep1: xt = gelu(attn) + h -> Xs (residual) and A tiles (next operand)
#pragma unroll
    for (int mt = 0; mt < 2; mt++)
#pragma unroll
        for (int j = 0; j < 8; j++) {
            int row = m0 + mt * 16 + qr, col = n0 + j * 8 + qc;
#pragma unroll
            for (int h = 0; h < 2; h++) {
                int r = row + h * 8;
                float x0 = gelu_f(acc[mt][j][2*h])   + Xs[r * XST + col];
                float x1 = gelu_f(acc[mt][j][2*h+1]) + Xs[r * XST + col + 1];
                Xs[r * XST + col] = x0; Xs[r * XST + col + 1] = x1;
                uint32_t lw, hw = split_pack(x0, x1, lw);
                uint32_t a = taddr(r, col);
                *(uint32_t*)(Ahi + a) = hw; *(uint32_t*)(Alo + a) = lw;
            }
        }
    load_trans(Bhi, Blo, f1w, D, tid);       // [o][c]
    __syncthreads();

    float acc2[2][8][4] = {};
    gemm_split(sAhi, sAlo, sBhi, sBlo, acc2, lane, m0, n0);  // u = xt @ f1w
    __syncthreads();

    // ep2: g = gelu(u + f1b) -> A tiles
#pragma unroll
    for (int mt = 0; mt < 2; mt++)
#pragma unroll
        for (int j = 0; j < 8; j++) {
            int row = m0 + mt * 16 + qr, col = n0 + j * 8 + qc;
#pragma unroll
            for (int h = 0; h < 2; h++) {
                int r = row + h * 8;
                float g0 = gelu_f(acc2[mt][j][2*h]   + ctrl[col]);
                float g1 = gelu_f(acc2[mt][j][2*h+1] + ctrl[col + 1]);
                uint32_t lw, hw = split_pack(g0, g1, lw);
                uint32_t a = taddr(r, col);
                *(uint32_t*)(Ahi + a) = hw; *(uint32_t*)(Alo + a) = lw;
            }
        }
    load_trans(Bhi, Blo, f2w, D, tid);
    __syncthreads();

    float acc3[2][8][4] = {};
    gemm_split(sAhi, sAlo, sBhi, sBlo, acc3, lane, m0, n0);  // r = g @ f2w

    // ep3: out = xt + r + f2b
#pragma unroll
    for (int mt = 0; mt < 2; mt++)
#pragma unroll
        for (int j = 0; j < 8; j++) {
            int row = m0 + mt * 16 + qr, col = n0 + j * 8 + qc;
#pragma unroll
            for (int h = 0; h < 2; h++) {
                int r = row + h * 8;
                float o0 = Xs[r * XST + col]     + acc3[mt][j][2*h]   + ctrl[128 + col];
                float o1 = Xs[r * XST + col + 1] + acc3[mt][j][2*h+1] + ctrl[128 + col + 1];
                *(float2*)&g_h[(tok0 + r) * D + col] = make_float2(o0, o1);
            }
        }
}

// ---------------- gconv map (2 GEMMs accumulated in regs) --------------------
__global__ __launch_bounds__(256, 1)
void gconv_map_kernel(const float* __restrict__ Bm, const float* __restrict__ ww,
                      const float* __restrict__ wb, int act) {
    TILE_PTRS(); WARP_SETUP();
    float* Xs = (float*)(dsm + OFF_X);
    int b = blockIdx.x >> 6;
    int n0t = (blockIdx.x & 63) * 128;
    size_t tok0 = (size_t)b * NTOK + n0t;

    if (tid < 128) ctrl[tid] = wb[tid];
    load_direct(Ahi, Alo, Bm + (size_t)n0t * KM, KM, tid);       // [t][k]
    load_direct(Bhi, Blo, g_sc + (size_t)b * D * KM, KM, tid);   // [o][k] = Yt^T
    for (int idx = tid; idx < 128 * 128; idx += 256)
        Xs[(idx >> 7) * XST + (idx & 127)] = g_h[(tok0 + (idx >> 7)) * D + (idx & 127)];
    __syncthreads();

    float acc[2][8][4] = {};
    gemm_split(sAhi, sAlo, sBhi, sBlo, acc, lane, m0, n0);   // x1 = Btile @ Yt
    __syncthreads();

    // A = h (from Xs), B = ww^T; accumulate x2 into same acc
    for (int p = tid; p < 128 * 64; p += 256) {
        int r = p >> 6, c = (p & 63) << 1;
        uint32_t lw, hw = split_pack(Xs[r * XST + c], Xs[r * XST + c + 1], lw);
        uint32_t a = taddr(r, c);
        *(uint32_t*)(Ahi + a) = hw; *(uint32_t*)(Alo + a) = lw;
    }
    load_trans(Bhi, Blo, ww, D, tid);
    __syncthreads();
    gemm_split(sAhi, sAlo, sBhi, sBlo, acc, lane, m0, n0);   // += h @ W

#pragma unroll
    for (int mt = 0; mt < 2; mt++)
#pragma unroll
        for (int j = 0; j < 8; j++) {
            int row = m0 + mt * 16 + qr, col = n0 + j * 8 + qc;
#pragma unroll
            for (int h = 0; h < 2; h++) {
                int r = row + h * 8;
                float z0 = acc[mt][j][2*h]   + ctrl[col];
                float z1 = acc[mt][j][2*h+1] + ctrl[col + 1];
                if (act) { z0 = gelu_f(z0); z1 = gelu_f(z1); }
                *(float2*)&g_h[(tok0 + r) * D + col] =
                    make_float2(Xs[r * XST + col] + z0, Xs[r * XST + col + 1] + z1);
            }
        }
}

// ---------------- head --------------------------------------------------------
__global__ __launch_bounds__(256, 1)
void head_kernel(const float* __restrict__ fc1w, const float* __restrict__ fc1b,
                 const float* __restrict__ fc2w, const float* __restrict__ fc2b,
                 float* __restrict__ out) {
    TILE_PTRS(); WARP_SETUP();
    int b = blockIdx.x >> 6;
    int n0t = (blockIdx.x & 63) * 128;
    size_t tok0 = (size_t)b * NTOK + n0t;
    int wn = wid >> 2;

    if (tid < 128) { ctrl[tid] = fc1b[tid]; ctrl[128 + tid] = fc2w[tid]; }
    float* partial = ctrl + 256;   // [2][128]
    load_direct(Ahi, Alo, g_h + tok0 * D, D, tid);   // [t][c]
    load_trans(Bhi, Blo, fc1w, D, tid);              // [o][c]
    __syncthreads();

    float acc[2][8][4] = {};
    gemm_split(sAhi, sAlo, sBhi, sBlo, acc, lane, m0, n0);

    float s[2][2] = {};
#pragma unroll
    for (int mt = 0; mt < 2; mt++)
#pragma unroll
        for (int j = 0; j < 8; j++) {
            int col = n0 + j * 8 + qc;
            s[mt][0] += gelu_f(acc[mt][j][0] + ctrl[col])     * ctrl[128 + col]
                      + gelu_f(acc[mt][j][1] + ctrl[col + 1]) * ctrl[128 + col + 1];
            s[mt][1] += gelu_f(acc[mt][j][2] + ctrl[col])     * ctrl[128 + col]
                      + gelu_f(acc[mt][j][3] + ctrl[col + 1]) * ctrl[128 + col + 1];
        }
#pragma unroll
    for (int mt = 0; mt < 2; mt++)
#pragma unroll
        for (int h = 0; h < 2; h++) {
            s[mt][h] += __shfl_xor_sync(0xffffffffu, s[mt][h], 1);
            s[mt][h] += __shfl_xor_sync(0xffffffffu, s[mt][h], 2);
        }
    if ((lane & 3) == 0) {
#pragma unroll
        for (int mt = 0; mt < 2; mt++) {
            partial[wn * 128 + m0 + mt * 16 + qr]     = s[mt][0];
            partial[wn * 128 + m0 + mt * 16 + qr + 8] = s[mt][1];
        }
    }
    __syncthreads();
    if (tid < 128)
        out[tok0 + tid] = partial[tid] + partial[128 + tid] + fc2b[0];
}

// ---------------- launch ------------------------------------------------------
extern "C" void kernel_launch(void* const* d_in, const int* in_sizes, int n_in,
                              void* d_out, int out_size) {
    const float* x      = (const float*)d_in[0];
    const float* Bm     = (const float*)d_in[1];
    const float* fc0_w1 = (const float*)d_in[2];
    const float* fc0_b1 = (const float*)d_in[3];
    const float* fc0_w2 = (const float*)d_in[4];
    const float* fc0_b2 = (const float*)d_in[5];
    const float* a0_wk  = (const float*)d_in[6];
    const float* a0_bk  = (const float*)d_in[7];
    const float* a0_f1w = (const float*)d_in[8];
    const float* a0_f1b = (const float*)d_in[9];
    const float* a0_f2w = (const float*)d_in[10];
    const float* a0_f2b = (const float*)d_in[11];
    const float* c1_w   = (const float*)d_in[12];
    const float* w1_w   = (const float*)d_in[13];
    const float* w1_b   = (const float*)d_in[14];
    const float* a2_wk  = (const float*)d_in[15];
    const float* a2_bk  = (const float*)d_in[16];
    const float* a2_f1w = (const float*)d_in[17];
    const float* a2_f1b = (const float*)d_in[18];
    const float* a2_f2w = (const float*)d_in[19];
    const float* a2_f2b = (const float*)d_in[20];
    const float* c3_w   = (const float*)d_in[21];
    const float* w3_w   = (const float*)d_in[22];
    const float* w3_b   = (const float*)d_in[23];
    const float* fc1_w  = (const float*)d_in[24];
    const float* fc1_b  = (const float*)d_in[25];
    const float* fc2_w  = (const float*)d_in[26];
    const float* fc2_b  = (const float*)d_in[27];
    float* out = (float*)d_out;

    const int SM2 = (2 * D * AST + 1024) * sizeof(float);
    cudaFuncSetAttribute((const void*)fc0_kernel,       cudaFuncAttributeMaxDynamicSharedMemorySize, SM_MID);
    cudaFuncSetAttribute((const void*)reduce_kernel,    cudaFuncAttributeMaxDynamicSharedMemorySize, SM_MID);
    cudaFuncSetAttribute((const void*)attn_map_kernel,  cudaFuncAttributeMaxDynamicSharedMemorySize, SM_BIG);
    cudaFuncSetAttribute((const void*)gconv_map_kernel, cudaFuncAttributeMaxDynamicSharedMemorySize, SM_BIG);
    cudaFuncSetAttribute((const void*)head_kernel,      cudaFuncAttributeMaxDynamicSharedMemorySize, SM_MID);
    cudaFuncSetAttribute((const void*)score_kernel,     cudaFuncAttributeMaxDynamicSharedMemorySize, SM2);

    colb_kernel<<<32, 128>>>(Bm);
    transpose_w_kernel<<<dim3(512, 4), dim3(32, 8)>>>(c1_w, 0);
    transpose_w_kernel<<<dim3(512, 4), dim3(32, 8)>>>(c3_w, 1);

    fc0_kernel<<<NTILES, 256, SM_MID>>>(x, fc0_w1, fc0_b1, fc0_w2, fc0_b2);

    reduce_kernel<<<dim3(NCHUNK, BB), 256, SM_MID>>>(Bm);
    reduce2_kernel<<<dim3(64, BB), 256>>>();
    score_kernel<<<BB, 256, SM2>>>(a0_wk, a0_bk);
    attn_map_kernel<<<NTILES, 256, SM_BIG>>>(Bm, a0_f1w, a0_f1b, a0_f2w, a0_f2b);

    reduce_kernel<<<dim3(NCHUNK, BB), 256, SM_MID>>>(Bm);
    reduce2_kernel<<<dim3(64, BB), 256>>>();
    gconv_modes_kernel<<<KM, 256>>>(0);
    gconv_map_kernel<<<NTILES, 256, SM_BIG>>>(Bm, w1_w, w1_b, 1);

    reduce_kernel<<<dim3(NCHUNK, BB), 256, SM_MID>>>(Bm);
    reduce2_kernel<<<dim3(64, BB), 256>>>();
    score_kernel<<<BB, 256, SM2>>>(a2_wk, a2_bk);
    attn_map_kernel<<<NTILES, 256, SM_BIG>>>(Bm, a2_f1w, a2_f1b, a2_f2w, a2_f2b);

    reduce_kernel<<<dim3(NCHUNK, BB), 256, SM_MID>>>(Bm);
    reduce2_kernel<<<dim3(64, BB), 256>>>();
    gconv_modes_kernel<<<KM, 256>>>(1);
    gconv_map_kernel<<<NTILES, 256, SM_BIG>>>(Bm, w3_w, w3_b, 0);

    head_kernel<<<NTILES, 256, SM_MID>>>(fc1_w, fc1_b, fc2_w, fc2_b, out);
}

// round 5
// speedup vs baseline: 1.6859x; 1.0448x over previous
#include <cuda_runtime.h>
#include <cuda_bf16.h>
#include <math.h>
#include <cstdint>

#define D     128
#define KM    128
#define NTOK  8192
#define BB    16
#define NCHUNK 16
#define NTILES ((BB*NTOK)/128)   // 1024
#define XST   129                // padded fp32 stage stride
#define NTH   512

// smem tile: 128 rows x 128 bf16 cols, 256 B/row, swizzled
#define TILEB 32768
#define OFF_AHI 0
#define OFF_ALO TILEB
#define OFF_BHI (2*TILEB)
#define OFF_BLO (3*TILEB)
#define OFF_CTRL (4*TILEB)            // 131072, 4 KB ctrl
#define OFF_X    (OFF_CTRL + 4096)    // fp32 stage 128*129*4 = 66048
#define SM_MID   OFF_X                // 135168
#define SM_BIG   (OFF_X + 66048)      // 201216

// ---------------- scratch ----------------------------------------------------
__device__ float g_h   [BB*NTOK*D];
__device__ float g_part[BB*NCHUNK*D*KM];
__device__ float g_S   [BB*D*KM];
__device__ float g_sc  [BB*D*KM];          // score^T [b][v][kd]  /  Yt^T [b][o][k]
__device__ float g_c1t [KM*D*D];
__device__ float g_c3t [KM*D*D];
__device__ float g_colb[32*KM];

// ---------------- helpers ----------------------------------------------------
__device__ __forceinline__ uint32_t smem_u32(const void* p) {
    uint32_t a;
    asm("{ .reg .u64 t; cvta.to.shared.u64 t, %1; cvt.u32.u64 %0, t; }" : "=r"(a) : "l"(p));
    return a;
}
__device__ __forceinline__ float gelu_f(float x) {
    return 0.5f * x * (1.0f + erff(x * 0.7071067811865475f));
}
// swizzled byte addr of tile element (row r, col c) ; c even for u32 stores
__device__ __forceinline__ uint32_t taddr(int r, int c) {
    return (uint32_t)(r * 256 + ((c << 1) ^ ((r & 7) << 4)));
}
__device__ __forceinline__ uint32_t split_pack(float x0, float x1, uint32_t& lop) {
    __nv_bfloat16 h0 = __float2bfloat16(x0);
    __nv_bfloat16 h1 = __float2bfloat16(x1);
    __nv_bfloat16 l0 = __float2bfloat16(x0 - __bfloat162float(h0));
    __nv_bfloat16 l1 = __float2bfloat16(x1 - __bfloat162float(h1));
    __nv_bfloat162 hp; hp.x = h0; hp.y = h1;
    __nv_bfloat162 lp; lp.x = l0; lp.y = l1;
    lop = *(uint32_t*)&lp;
    return *(uint32_t*)&hp;
}

__device__ __forceinline__ void ldsm4(uint32_t a[4], uint32_t addr) {
    asm volatile("ldmatrix.sync.aligned.m8n8.x4.shared.b16 {%0,%1,%2,%3}, [%4];"
        : "=r"(a[0]), "=r"(a[1]), "=r"(a[2]), "=r"(a[3]) : "r"(addr));
}
__device__ __forceinline__ void ldsm2(uint32_t b[2], uint32_t addr) {
    asm volatile("ldmatrix.sync.aligned.m8n8.x2.shared.b16 {%0,%1}, [%2];"
        : "=r"(b[0]), "=r"(b[1]) : "r"(addr));
}
__device__ __forceinline__ void mma16816(float c[4], const uint32_t a[4], const uint32_t b[2]) {
    asm volatile("mma.sync.aligned.m16n8k16.row.col.f32.bf16.bf16.f32 "
        "{%0,%1,%2,%3}, {%4,%5,%6,%7}, {%8,%9}, {%0,%1,%2,%3};"
        : "+f"(c[0]), "+f"(c[1]), "+f"(c[2]), "+f"(c[3])
        : "r"(a[0]), "r"(a[1]), "r"(a[2]), "r"(a[3]), "r"(b[0]), "r"(b[1]));
}

// C[t][o] += A[t][k] * B[o][k], 3-pass hi/lo split. Warp tile 32x32: acc[2][4][4].
__device__ __forceinline__ void gemm_split(uint32_t sAhi, uint32_t sAlo,
                                           uint32_t sBhi, uint32_t sBlo,
                                           float acc[2][4][4], int lane, int m0, int n0) {
#pragma unroll
    for (int k0 = 0; k0 < 128; k0 += 16) {
        uint32_t aoff = taddr(m0 + (lane & 15), k0 + ((lane >> 4) << 3));
        uint32_t aoff2 = taddr(m0 + 16 + (lane & 15), k0 + ((lane >> 4) << 3));
        uint32_t ah0[4], ah1[4], al0[4], al1[4];
        ldsm4(ah0, sAhi + aoff);
        ldsm4(ah1, sAhi + aoff2);
        ldsm4(al0, sAlo + aoff);
        ldsm4(al1, sAlo + aoff2);
#pragma unroll
        for (int j = 0; j < 4; j++) {
            uint32_t boff = taddr(n0 + j * 8 + (lane & 7), k0 + ((lane >> 3) & 1) * 8);
            uint32_t bh[2], bl[2];
            ldsm2(bh, sBhi + boff);
            ldsm2(bl, sBlo + boff);
            mma16816(acc[0][j], ah0, bh);
            mma16816(acc[1][j], ah1, bh);
            mma16816(acc[0][j], ah0, bl);
            mma16816(acc[1][j], ah1, bl);
            mma16816(acc[0][j], al0, bh);
            mma16816(acc[1][j], al1, bh);
        }
    }
}

// tile[r][c] = G[r*ldg + c]
__device__ __forceinline__ void load_direct(char* hi, char* lo, const float* __restrict__ G,
                                            int ldg, int tid) {
    for (int p = tid; p < 128 * 64; p += NTH) {
        int r = p >> 6, c = (p & 63) << 1;
        float2 v = *(const float2*)(G + r * ldg + c);
        uint32_t lw, hw = split_pack(v.x, v.y, lw);
        uint32_t a = taddr(r, c);
        *(uint32_t*)(hi + a) = hw; *(uint32_t*)(lo + a) = lw;
    }
}
// tile[r][c] = G[c*ldg + r]
__device__ __forceinline__ void load_trans(char* hi, char* lo, const float* __restrict__ G,
                                           int ldg, int tid) {
    for (int p = tid; p < 128 * 64; p += NTH) {
        int r = p & 127, c = (p >> 7) << 1;
        float v0 = G[c * ldg + r], v1 = G[(c + 1) * ldg + r];
        uint32_t lw, hw = split_pack(v0, v1, lw);
        uint32_t a = taddr(r, c);
        *(uint32_t*)(hi + a) = hw; *(uint32_t*)(lo + a) = lw;
    }
}

#define WARP_SETUP()                                                 \
    int tid = threadIdx.x;                                           \
    int lane = tid & 31, wid = tid >> 5;                             \
    int m0 = (wid & 3) * 32, n0 = (wid >> 2) * 32;                   \
    int qr = lane >> 2, qc = (lane & 3) * 2;                         \
    (void)qr; (void)qc;

#define TILE_PTRS()                                                  \
    extern __shared__ __align__(1024) char dsm[];                    \
    char* Ahi = dsm + OFF_AHI; char* Alo = dsm + OFF_ALO;            \
    char* Bhi = dsm + OFF_BHI; char* Blo = dsm + OFF_BLO;            \
    uint32_t sb = smem_u32(dsm);                                     \
    uint32_t sAhi = sb + OFF_AHI, sAlo = sb + OFF_ALO;               \
    uint32_t sBhi = sb + OFF_BHI, sBlo = sb + OFF_BLO;               \
    float* ctrl = (float*)(dsm + OFF_CTRL);                          \
    (void)ctrl;

// ---------------- small prep kernels ----------------------------------------
__global__ void colb_kernel(const float* __restrict__ Bm) {
    int k = threadIdx.x, p = blockIdx.x;
    float s = 0.f;
    int r0 = p * 256;
    for (int r = 0; r < 256; r++) s += Bm[(r0 + r) * KM + k];
    g_colb[p * KM + k] = s;
}

__global__ void transpose_w_kernel(const float* __restrict__ W, int which) {
    float* Wt = which ? g_c3t : g_c1t;
    __shared__ float tile[32][33];
    int x0 = blockIdx.x * 32, y0 = blockIdx.y * 32;
    int tx = threadIdx.x, ty = threadIdx.y;
#pragma unroll
    for (int r = 0; r < 32; r += 8)
        tile[ty + r][tx] = W[(x0 + ty + r) * KM + y0 + tx];
    __syncthreads();
#pragma unroll
    for (int r = 0; r < 32; r += 8)
        Wt[(y0 + ty + r) * (D * D) + x0 + tx] = tile[tx][ty + r];
}

__global__ void reduce2_kernel() {
    int e = blockIdx.x * 256 + threadIdx.x;
    int b = blockIdx.y;
    float s = 0.f;
#pragma unroll
    for (int cz = 0; cz < NCHUNK; cz++)
        s += g_part[(b * NCHUNK + cz) * D * KM + e];
    g_S[b * D * KM + e] = s;
}

#define AST 132
__device__ __forceinline__ void gemm8x8(const float* __restrict__ A, const float* __restrict__ W,
                                        float (&acc)[8][8], int ty, int tx, int kdim) {
    const float* ap = A + ty * 8;
    const float* wp = W + tx * 8;
#pragma unroll 4
    for (int k = 0; k < kdim; k++) {
        float4 a0 = *(const float4*)(ap + k * AST);
        float4 a1 = *(const float4*)(ap + k * AST + 4);
        float4 w0 = *(const float4*)(wp + k * AST);
        float4 w1 = *(const float4*)(wp + k * AST + 4);
        float a[8] = {a0.x,a0.y,a0.z,a0.w,a1.x,a1.y,a1.z,a1.w};
        float w[8] = {w0.x,w0.y,w0.z,w0.w,w1.x,w1.y,w1.z,w1.w};
#pragma unroll
        for (int i = 0; i < 8; i++)
#pragma unroll
            for (int j = 0; j < 8; j++)
                acc[i][j] = fmaf(a[i], w[j], acc[i][j]);
    }
}

// score^T[b][v][kd] = sum_c wk[c][kd] S[c][v] + bk[kd]*colB[v]
__global__ void score_kernel(const float* __restrict__ wk, const float* __restrict__ bk) {
    extern __shared__ float sm[];
    float* As = sm;
    float* Ws = sm + D * AST;
    float* cb = Ws + D * AST;
    int b = blockIdx.x, tid = threadIdx.x;
    if (tid < KM) {
        float s = 0.f;
        for (int p = 0; p < 32; p++) s += g_colb[p * KM + tid];
        cb[tid] = s;
    }
    for (int idx = tid; idx < D * D; idx += 256) {
        As[(idx >> 7) * AST + (idx & 127)] = wk[idx];
        Ws[(idx >> 7) * AST + (idx & 127)] = g_S[b * D * KM + idx];
    }
    __syncthreads();
    int ty = tid >> 4, tx = tid & 15;
    float acc[8][8] = {};
    gemm8x8(As, Ws, acc, ty, tx, D);
#pragma unroll
    for (int i = 0; i < 8; i++) {
        float bkk = bk[ty * 8 + i];
#pragma unroll
        for (int j = 0; j < 8; j++)
            g_sc[(b * D + tx * 8 + j) * KM + ty * 8 + i] = acc[i][j] + bkk * cb[tx * 8 + j];
    }
}

// Yt^T[b][o][k] = sum_i S[b][i][k] W[k][i][o]
__global__ void gconv_modes_kernel(int which) {
    const float* Wt = which ? g_c3t : g_c1t;
    __shared__ float Ss[BB * D];
    int k = blockIdx.x, tid = threadIdx.x;
    for (int idx = tid; idx < BB * D; idx += 256)
        Ss[idx] = g_S[((idx >> 7) * D + (idx & 127)) * KM + k];
    __syncthreads();
    int hi = tid >> 7, o = tid & 127;
    float acc[8] = {};
    for (int i = 0; i < D; i++) {
        float w = Wt[(k * D + i) * D + o];
#pragma unroll
        for (int q = 0; q < 8; q++)
            acc[q] = fmaf(Ss[(hi * 8 + q) * D + i], w, acc[q]);
    }
#pragma unroll
    for (int q = 0; q < 8; q++)
        g_sc[((hi * 8 + q) * D + o) * KM + k] = acc[q];
}

// ---------------- fc0 ---------------------------------------------------------
__global__ __launch_bounds__(NTH, 1)
void fc0_kernel(const float* __restrict__ x, const float* __restrict__ w1,
                const float* __restrict__ b1, const float* __restrict__ w2,
                const float* __restrict__ b2) {
    TILE_PTRS(); WARP_SETUP();
    float* xs  = ctrl;          // 256
    float* w1s = ctrl + 256;    // 256
    float* b1s = ctrl + 512;    // 128
    float* b2s = ctrl + 640;    // 128
    int tok0 = blockIdx.x * 128;

    if (tid < 256) { xs[tid] = x[tok0 * 2 + tid]; w1s[tid] = w1[tid]; }
    if (tid < 128) { b1s[tid] = b1[tid]; b2s[tid] = b2[tid]; }
    __syncthreads();

    for (int p = tid; p < 128 * 64; p += NTH) {
        int r = p >> 6, c = (p & 63) << 1;
        float v0 = gelu_f(xs[2*r] * w1s[c]   + xs[2*r+1] * w1s[128+c]   + b1s[c]);
        float v1 = gelu_f(xs[2*r] * w1s[c+1] + xs[2*r+1] * w1s[128+c+1] + b1s[c+1]);
        uint32_t lw, hw = split_pack(v0, v1, lw);
        uint32_t a = taddr(r, c);
        *(uint32_t*)(Ahi + a) = hw; *(uint32_t*)(Alo + a) = lw;
    }
    load_trans(Bhi, Blo, w2, D, tid);     // B[o][c] = w2[c][o]
    __syncthreads();

    float acc[2][4][4] = {};
    gemm_split(sAhi, sAlo, sBhi, sBlo, acc, lane, m0, n0);

#pragma unroll
    for (int mt = 0; mt < 2; mt++)
#pragma unroll
        for (int j = 0; j < 4; j++) {
            int row = m0 + mt * 16 + qr, col = n0 + j * 8 + qc;
            *(float2*)&g_h[(size_t)(tok0 + row) * D + col] =
                make_float2(acc[mt][j][0] + b2s[col], acc[mt][j][1] + b2s[col + 1]);
            *(float2*)&g_h[(size_t)(tok0 + row + 8) * D + col] =
                make_float2(acc[mt][j][2] + b2s[col], acc[mt][j][3] + b2s[col + 1]);
        }
}

// ---------------- reduce: part[c][k] = sum_t h[t][c] B[t][k] (512-token chunk)
__global__ __launch_bounds__(NTH, 1)
void reduce_kernel(const float* __restrict__ Bm) {
    TILE_PTRS(); WARP_SETUP();
    int cz = blockIdx.x, b = blockIdx.y;
    float acc[2][4][4] = {};
    for (int sub = 0; sub < 4; sub++) {
        int nb = cz * 512 + sub * 128;
        load_trans(Ahi, Alo, g_h + (size_t)(b * NTOK + nb) * D, D, tid);  // [c][t]
        load_trans(Bhi, Blo, Bm + (size_t)nb * KM, KM, tid);              // [k][t]
        __syncthreads();
        gemm_split(sAhi, sAlo, sBhi, sBlo, acc, lane, m0, n0);
        __syncthreads();
    }
    size_t ob = (size_t)(b * NCHUNK + cz) * D * KM;
#pragma unroll
    for (int mt = 0; mt < 2; mt++)
#pragma unroll
        for (int j = 0; j < 4; j++) {
            int row = m0 + mt * 16 + qr, col = n0 + j * 8 + qc;
            *(float2*)&g_part[ob + (size_t)row * KM + col] = make_float2(acc[mt][j][0], acc[mt][j][1]);
            *(float2*)&g_part[ob + (size_t)(row + 8) * KM + col] = make_float2(acc[mt][j][2], acc[mt][j][3]);
        }
}

// ---------------- attention map (3 chained GEMMs, reg accumulators) ----------
__global__ __launch_bounds__(NTH, 1)
void attn_map_kernel(const float* __restrict__ Bm,  const float* __restrict__ f1w,
                     const float* __restrict__ f1b, const float* __restrict__ f2w,
                     const float* __restrict__ f2b) {
    TILE_PTRS(); WARP_SETUP();
    float* Xs = (float*)(dsm + OFF_X);
    int b = blockIdx.x >> 6;
    int n0t = (blockIdx.x & 63) * 128;
    size_t tok0 = (size_t)b * NTOK + n0t;

    if (tid < 128) { ctrl[tid] = f1b[tid]; ctrl[128 + tid] = f2b[tid]; }
    load_direct(Ahi, Alo, Bm + (size_t)n0t * KM, KM, tid);       // [t][kd]
    load_direct(Bhi, Blo, g_sc + (size_t)b * D * KM, KM, tid);   // [v][kd]
    for (int idx = tid; idx < 128 * 128; idx += NTH)
        Xs[(idx >> 7) * XST + (idx & 127)] = g_h[(tok0 + (idx >> 7)) * D + (idx & 127)];
    __syncthreads();

    float acc[2][4][4] = {};
    gemm_split(sAhi, sAlo, sBhi, sBlo, acc, lane, m0, n0);   // attn
    __syncthreads();

    // ep1: xt = gelu(attn) + h -> Xs (residual) and A tiles (next operand)
#pragma unroll
    for (int mt = 0; mt < 2; mt++)
#pragma unroll
        for (int j = 0; j < 4; j++) {
            int row = m0 + mt * 16 + qr, col = n0 + j * 8 + qc;
#pragma unroll
            for (int h = 0; h < 2; h++) {
                int r = row + h * 8;
                float x0 = gelu_f(acc[mt][j][2*h])   + Xs[r * XST + col];
                float x1 = gelu_f(acc[mt][j][2*h+1]) + Xs[r * XST + col + 1];
                Xs[r * XST + col] = x0; Xs[r * XST + col + 1] = x1;
                uint32_t lw, hw = split_pack(x0, x1, lw);
                uint32_t a = taddr(r, col);
                *(uint32_t*)(Ahi + a) = hw; *(uint32_t*)(Alo + a) = lw;
            }
        }
    load_trans(Bhi, Blo, f1w, D, tid);       // [o][c]
    __syncthreads();

    float acc2[2][4][4] = {};
    gemm_split(sAhi, sAlo, sBhi, sBlo, acc2, lane, m0, n0);  // u = xt @ f1w
    __syncthreads();

    // ep2: g = gelu(u + f1b) -> A tiles
#pragma unroll
    for (int mt = 0; mt < 2; mt++)
#pragma unroll
        for (int j = 0; j < 4; j++) {
            int row = m0 + mt * 16 + qr, col = n0 + j * 8 + qc;
#pragma unroll
            for (int h = 0; h < 2; h++) {
                int r = row + h * 8;
                float g0 = gelu_f(acc2[mt][j][2*h]   + ctrl[col]);
                float g1 = gelu_f(acc2[mt][j][2*h+1] + ctrl[col + 1]);
                uint32_t lw, hw = split_pack(g0, g1, lw);
                uint32_t a = taddr(r, col);
                *(uint32_t*)(Ahi + a) = hw; *(uint32_t*)(Alo + a) = lw;
            }
        }
    load_trans(Bhi, Blo, f2w, D, tid);
    __syncthreads();

    float acc3[2][4][4] = {};
    gemm_split(sAhi, sAlo, sBhi, sBlo, acc3, lane, m0, n0);  // r = g @ f2w

    // ep3: out = xt + r + f2b
#pragma unroll
    for (int mt = 0; mt < 2; mt++)
#pragma unroll
        for (int j = 0; j < 4; j++) {
            int row = m0 + mt * 16 + qr, col = n0 + j * 8 + qc;
#pragma unroll
            for (int h = 0; h < 2; h++) {
                int r = row + h * 8;
                float o0 = Xs[r * XST + col]     + acc3[mt][j][2*h]   + ctrl[128 + col];
                float o1 = Xs[r * XST + col + 1] + acc3[mt][j][2*h+1] + ctrl[128 + col + 1];
                *(float2*)&g_h[(tok0 + r) * D + col] = make_float2(o0, o1);
            }
        }
}

// ---------------- gconv map (2 GEMMs accumulated in regs) --------------------
__global__ __launch_bounds__(NTH, 1)
void gconv_map_kernel(const float* __restrict__ Bm, const float* __restrict__ ww,
                      const float* __restrict__ wb, int act) {
    TILE_PTRS(); WARP_SETUP();
    float* Xs = (float*)(dsm + OFF_X);
    int b = blockIdx.x >> 6;
    int n0t = (blockIdx.x & 63) * 128;
    size_t tok0 = (size_t)b * NTOK + n0t;

    if (tid < 128) ctrl[tid] = wb[tid];
    load_direct(Ahi, Alo, Bm + (size_t)n0t * KM, KM, tid);       // [t][k]
    load_direct(Bhi, Blo, g_sc + (size_t)b * D * KM, KM, tid);   // [o][k] = Yt^T
    for (int idx = tid; idx < 128 * 128; idx += NTH)
        Xs[(idx >> 7) * XST + (idx & 127)] = g_h[(tok0 + (idx >> 7)) * D + (idx & 127)];
    __syncthreads();

    float acc[2][4][4] = {};
    gemm_split(sAhi, sAlo, sBhi, sBlo, acc, lane, m0, n0);   // x1 = Btile @ Yt
    __syncthreads();

    // A = h (from Xs), B = ww^T; accumulate x2 into same acc
    for (int p = tid; p < 128 * 64; p += NTH) {
        int r = p >> 6, c = (p & 63) << 1;
        uint32_t lw, hw = split_pack(Xs[r * XST + c], Xs[r * XST + c + 1], lw);
        uint32_t a = taddr(r, c);
        *(uint32_t*)(Ahi + a) = hw; *(uint32_t*)(Alo + a) = lw;
    }
    load_trans(Bhi, Blo, ww, D, tid);
    __syncthreads();
    gemm_split(sAhi, sAlo, sBhi, sBlo, acc, lane, m0, n0);   // += h @ W

#pragma unroll
    for (int mt = 0; mt < 2; mt++)
#pragma unroll
        for (int j = 0; j < 4; j++) {
            int row = m0 + mt * 16 + qr, col = n0 + j * 8 + qc;
#pragma unroll
            for (int h = 0; h < 2; h++) {
                int r = row + h * 8;
                float z0 = acc[mt][j][2*h]   + ctrl[col];
                float z1 = acc[mt][j][2*h+1] + ctrl[col + 1];
                if (act) { z0 = gelu_f(z0); z1 = gelu_f(z1); }
                *(float2*)&g_h[(tok0 + r) * D + col] =
                    make_float2(Xs[r * XST + col] + z0, Xs[r * XST + col + 1] + z1);
            }
        }
}

// ---------------- head --------------------------------------------------------
__global__ __launch_bounds__(NTH, 1)
void head_kernel(const float* __restrict__ fc1w, const float* __restrict__ fc1b,
                 const float* __restrict__ fc2w, const float* __restrict__ fc2b,
                 float* __restrict__ out) {
    TILE_PTRS(); WARP_SETUP();
    int b = blockIdx.x >> 6;
    int n0t = (blockIdx.x & 63) * 128;
    size_t tok0 = (size_t)b * NTOK + n0t;
    int wn = wid >> 2;

    if (tid < 128) { ctrl[tid] = fc1b[tid]; ctrl[128 + tid] = fc2w[tid]; }
    float* partial = ctrl + 256;   // [4][128]
    load_direct(Ahi, Alo, g_h + tok0 * D, D, tid);   // [t][c]
    load_trans(Bhi, Blo, fc1w, D, tid);              // [o][c]
    __syncthreads();

    float acc[2][4][4] = {};
    gemm_split(sAhi, sAlo, sBhi, sBlo, acc, lane, m0, n0);

    float s[2][2] = {};
#pragma unroll
    for (int mt = 0; mt < 2; mt++)
#pragma unroll
        for (int j = 0; j < 4; j++) {
            int col = n0 + j * 8 + qc;
            s[mt][0] += gelu_f(acc[mt][j][0] + ctrl[col])     * ctrl[128 + col]
                      + gelu_f(acc[mt][j][1] + ctrl[col + 1]) * ctrl[128 + col + 1];
            s[mt][1] += gelu_f(acc[mt][j][2] + ctrl[col])     * ctrl[128 + col]
                      + gelu_f(acc[mt][j][3] + ctrl[col + 1]) * ctrl[128 + col + 1];
        }
#pragma unroll
    for (int mt = 0; mt < 2; mt++)
#pragma unroll
        for (int h = 0; h < 2; h++) {
            s[mt][h] += __shfl_xor_sync(0xffffffffu, s[mt][h], 1);
            s[mt][h] += __shfl_xor_sync(0xffffffffu, s[mt][h], 2);
        }
    if ((lane & 3) == 0) {
#pragma unroll
        for (int mt = 0; mt < 2; mt++) {
            partial[wn * 128 + m0 + mt * 16 + qr]     = s[mt][0];
            partial[wn * 128 + m0 + mt * 16 + qr + 8] = s[mt][1];
        }
    }
    __syncthreads();
    if (tid < 128)
        out[tok0 + tid] = partial[tid] + partial[128 + tid] + partial[256 + tid]
                        + partial[384 + tid] + fc2b[0];
}

// ---------------- launch ------------------------------------------------------
extern "C" void kernel_launch(void* const* d_in, const int* in_sizes, int n_in,
                              void* d_out, int out_size) {
    const float* x      = (const float*)d_in[0];
    const float* Bm     = (const float*)d_in[1];
    const float* fc0_w1 = (const float*)d_in[2];
    const float* fc0_b1 = (const float*)d_in[3];
    const float* fc0_w2 = (const float*)d_in[4];
    const float* fc0_b2 = (const float*)d_in[5];
    const float* a0_wk  = (const float*)d_in[6];
    const float* a0_bk  = (const float*)d_in[7];
    const float* a0_f1w = (const float*)d_in[8];
    const float* a0_f1b = (const float*)d_in[9];
    const float* a0_f2w = (const float*)d_in[10];
    const float* a0_f2b = (const float*)d_in[11];
    const float* c1_w   = (const float*)d_in[12];
    const float* w1_w   = (const float*)d_in[13];
    const float* w1_b   = (const float*)d_in[14];
    const float* a2_wk  = (const float*)d_in[15];
    const float* a2_bk  = (const float*)d_in[16];
    const float* a2_f1w = (const float*)d_in[17];
    const float* a2_f1b = (const float*)d_in[18];
    const float* a2_f2w = (const float*)d_in[19];
    const float* a2_f2b = (const float*)d_in[20];
    const float* c3_w   = (const float*)d_in[21];
    const float* w3_w   = (const float*)d_in[22];
    const float* w3_b   = (const float*)d_in[23];
    const float* fc1_w  = (const float*)d_in[24];
    const float* fc1_b  = (const float*)d_in[25];
    const float* fc2_w  = (const float*)d_in[26];
    const float* fc2_b  = (const float*)d_in[27];
    float* out = (float*)d_out;

    const int SM2 = (2 * D * AST + 1024) * sizeof(float);
    cudaFuncSetAttribute((const void*)fc0_kernel,       cudaFuncAttributeMaxDynamicSharedMemorySize, SM_MID);
    cudaFuncSetAttribute((const void*)reduce_kernel,    cudaFuncAttributeMaxDynamicSharedMemorySize, SM_MID);
    cudaFuncSetAttribute((const void*)attn_map_kernel,  cudaFuncAttributeMaxDynamicSharedMemorySize, SM_BIG);
    cudaFuncSetAttribute((const void*)gconv_map_kernel, cudaFuncAttributeMaxDynamicSharedMemorySize, SM_BIG);
    cudaFuncSetAttribute((const void*)head_kernel,      cudaFuncAttributeMaxDynamicSharedMemorySize, SM_MID);
    cudaFuncSetAttribute((const void*)score_kernel,     cudaFuncAttributeMaxDynamicSharedMemorySize, SM2);

    colb_kernel<<<32, 128>>>(Bm);
    transpose_w_kernel<<<dim3(512, 4), dim3(32, 8)>>>(c1_w, 0);
    transpose_w_kernel<<<dim3(512, 4), dim3(32, 8)>>>(c3_w, 1);

    fc0_kernel<<<NTILES, NTH, SM_MID>>>(x, fc0_w1, fc0_b1, fc0_w2, fc0_b2);

    reduce_kernel<<<dim3(NCHUNK, BB), NTH, SM_MID>>>(Bm);
    reduce2_kernel<<<dim3(64, BB), 256>>>();
    score_kernel<<<BB, 256, SM2>>>(a0_wk, a0_bk);
    attn_map_kernel<<<NTILES, NTH, SM_BIG>>>(Bm, a0_f1w, a0_f1b, a0_f2w, a0_f2b);

    reduce_kernel<<<dim3(NCHUNK, BB), NTH, SM_MID>>>(Bm);
    reduce2_kernel<<<dim3(64, BB), 256>>>();
    gconv_modes_kernel<<<KM, 256>>>(0);
    gconv_map_kernel<<<NTILES, NTH, SM_BIG>>>(Bm, w1_w, w1_b, 1);

    reduce_kernel<<<dim3(NCHUNK, BB), NTH, SM_MID>>>(Bm);
    reduce2_kernel<<<dim3(64, BB), 256>>>();
    score_kernel<<<BB, 256, SM2>>>(a2_wk, a2_bk);
    attn_map_kernel<<<NTILES, NTH, SM_BIG>>>(Bm, a2_f1w, a2_f1b, a2_f2w, a2_f2b);

    reduce_kernel<<<dim3(NCHUNK, BB), NTH, SM_MID>>>(Bm);
    reduce2_kernel<<<dim3(64, BB), 256>>>();
    gconv_modes_kernel<<<KM, 256>>>(1);
    gconv_map_kernel<<<NTILES, NTH, SM_BIG>>>(Bm, w3_w, w3_b, 0);

    head_kernel<<<NTILES, NTH, SM_MID>>>(fc1_w, fc1_b, fc2_w, fc2_b, out);
}

// round 8
// speedup vs baseline: 2.5816x; 1.5313x over previous
#include <cuda_runtime.h>
#include <cuda_bf16.h>
#include <math.h>
#include <cstdint>

#define D     128
#define KM    128
#define NTOK  8192
#define BB    16
#define NCHUNK 16
#define NTILES 1024
#define NTH   512
#define IMGB  32768            // one 128x128 bf16 tile image

// smem slots
#define OFF_AHI 0
#define OFF_ALO 32768
#define OFF_BHI 65536
#define OFF_BLO 98304
#define OFF_XHI 131072
#define OFF_XLO 163840
#define CS_MID  131072
#define CS_BIG  196608
#define SM_MID  (CS_MID + 4096)   // 135168
#define SM_BIG  (CS_BIG + 4096)   // 200704

// ---------------- global scratch (tile images are swizzled smem replicas) ----
__device__ __align__(16) char g_himg [(size_t)NTILES*2*IMGB];  // h hi/lo, 64MB
__device__ __align__(16) char g_Bimg [64*2*IMGB];              // B matrix tiles
__device__ __align__(16) char g_wimg [8*2*IMGB];               // weights [o][ci]
__device__ __align__(16) char g_scimg[BB*2*IMGB];              // score / Yt imgs
__device__ float g_part[BB*NCHUNK*D*KM];
__device__ float g_S   [BB*D*KM];
__device__ float g_c1t [KM*D*D];
__device__ float g_c3t [KM*D*D];
__device__ float g_colb[32*KM];

#define HIMG(t,hl)  (g_himg  + ((size_t)(t)*2 + (hl))*IMGB)
#define BIMG(t,hl)  (g_Bimg  + ((size_t)(t)*2 + (hl))*IMGB)
#define WIMG(w,hl)  (g_wimg  + ((size_t)(w)*2 + (hl))*IMGB)
#define SCIMG(b,hl) (g_scimg + ((size_t)(b)*2 + (hl))*IMGB)
// weight image index: 0 fc0_w2, 1 a0_f1w, 2 a0_f2w, 3 w1_w, 4 a2_f1w, 5 a2_f2w, 6 w3_w, 7 fc1_w

// ---------------- helpers ----------------------------------------------------
__device__ __forceinline__ uint32_t smem_u32(const void* p) {
    uint32_t a;
    asm("{ .reg .u64 t; cvta.to.shared.u64 t, %1; cvt.u32.u64 %0, t; }" : "=r"(a) : "l"(p));
    return a;
}
__device__ __forceinline__ float gelu_f(float x) {
    return 0.5f * x * (1.0f + erff(x * 0.7071067811865475f));
}
__device__ __forceinline__ uint32_t taddr(int r, int c) {   // byte offset in image
    return (uint32_t)(r * 256 + ((c << 1) ^ ((r & 7) << 4)));
}
__device__ __forceinline__ uint32_t split_pack(float x0, float x1, uint32_t& lop) {
    __nv_bfloat16 h0 = __float2bfloat16(x0);
    __nv_bfloat16 h1 = __float2bfloat16(x1);
    __nv_bfloat16 l0 = __float2bfloat16(x0 - __bfloat162float(h0));
    __nv_bfloat16 l1 = __float2bfloat16(x1 - __bfloat162float(h1));
    __nv_bfloat162 hp; hp.x = h0; hp.y = h1;
    __nv_bfloat162 lp; lp.x = l0; lp.y = l1;
    lop = *(uint32_t*)&lp;
    return *(uint32_t*)&hp;
}
__device__ __forceinline__ float2 unpack_split(uint32_t hw, uint32_t lw) {
    __nv_bfloat162 hp = *(__nv_bfloat162*)&hw;
    __nv_bfloat162 lp = *(__nv_bfloat162*)&lw;
    return make_float2(__bfloat162float(hp.x) + __bfloat162float(lp.x),
                       __bfloat162float(hp.y) + __bfloat162float(lp.y));
}
__device__ __forceinline__ void store_split(char* ihi, char* ilo, int r, int c,
                                            float v0, float v1) {
    uint32_t lw, hw = split_pack(v0, v1, lw);
    uint32_t a = taddr(r, c);
    *(uint32_t*)(ihi + a) = hw; *(uint32_t*)(ilo + a) = lw;
}

// cp.async
__device__ __forceinline__ void cp16(uint32_t s, const void* g) {
    asm volatile("cp.async.cg.shared.global [%0], [%1], 16;" :: "r"(s), "l"(g) : "memory");
}
#define CP_COMMIT() asm volatile("cp.async.commit_group;" ::: "memory")
#define CP_WAIT0()  asm volatile("cp.async.wait_group 0;" ::: "memory")
__device__ __forceinline__ void cpimg(uint32_t sdst, const char* g, int tid) {
    for (int i = tid; i < 2048; i += NTH) cp16(sdst + i * 16, g + i * 16);
}

// ldmatrix / mma
__device__ __forceinline__ void ldsm4(uint32_t a[4], uint32_t addr) {
    asm volatile("ldmatrix.sync.aligned.m8n8.x4.shared.b16 {%0,%1,%2,%3}, [%4];"
        : "=r"(a[0]), "=r"(a[1]), "=r"(a[2]), "=r"(a[3]) : "r"(addr));
}
__device__ __forceinline__ void ldsm2(uint32_t b[2], uint32_t addr) {
    asm volatile("ldmatrix.sync.aligned.m8n8.x2.shared.b16 {%0,%1}, [%2];"
        : "=r"(b[0]), "=r"(b[1]) : "r"(addr));
}
__device__ __forceinline__ void ldsm4t(uint32_t a[4], uint32_t addr) {
    asm volatile("ldmatrix.sync.aligned.m8n8.x4.trans.shared.b16 {%0,%1,%2,%3}, [%4];"
        : "=r"(a[0]), "=r"(a[1]), "=r"(a[2]), "=r"(a[3]) : "r"(addr));
}
__device__ __forceinline__ void ldsm2t(uint32_t b[2], uint32_t addr) {
    asm volatile("ldmatrix.sync.aligned.m8n8.x2.trans.shared.b16 {%0,%1}, [%2];"
        : "=r"(b[0]), "=r"(b[1]) : "r"(addr));
}
__device__ __forceinline__ void mma16816(float c[4], const uint32_t a[4], const uint32_t b[2]) {
    asm volatile("mma.sync.aligned.m16n8k16.row.col.f32.bf16.bf16.f32 "
        "{%0,%1,%2,%3}, {%4,%5,%6,%7}, {%8,%9}, {%0,%1,%2,%3};"
        : "+f"(c[0]), "+f"(c[1]), "+f"(c[2]), "+f"(c[3])
        : "r"(a[0]), "r"(a[1]), "r"(a[2]), "r"(a[3]), "r"(b[0]), "r"(b[1]));
}

// C[m][n] += A[m][k] B[n][k], A image [m][k], B image [n][k]; 3-pass split.
__device__ __forceinline__ void gemm_split(uint32_t sAhi, uint32_t sAlo,
                                           uint32_t sBhi, uint32_t sBlo,
                                           float acc[2][4][4], int lane, int m0, int n0) {
#pragma unroll
    for (int k0 = 0; k0 < 128; k0 += 16) {
        uint32_t aoff  = taddr(m0 + (lane & 15), k0 + ((lane >> 4) << 3));
        uint32_t aoff2 = taddr(m0 + 16 + (lane & 15), k0 + ((lane >> 4) << 3));
        uint32_t ah0[4], ah1[4], al0[4], al1[4];
        ldsm4(ah0, sAhi + aoff);  ldsm4(ah1, sAhi + aoff2);
        ldsm4(al0, sAlo + aoff);  ldsm4(al1, sAlo + aoff2);
#pragma unroll
        for (int j = 0; j < 4; j++) {
            uint32_t boff = taddr(n0 + j * 8 + (lane & 7), k0 + ((lane >> 3) & 1) * 8);
            uint32_t bh[2], bl[2];
            ldsm2(bh, sBhi + boff); ldsm2(bl, sBlo + boff);
            mma16816(acc[0][j], ah0, bh); mma16816(acc[1][j], ah1, bh);
            mma16816(acc[0][j], ah0, bl); mma16816(acc[1][j], ah1, bl);
            mma16816(acc[0][j], al0, bh); mma16816(acc[1][j], al1, bh);
        }
    }
}

// C[m][n] += A[t][m] B[t][n] (both operands t-major images, trans ldmatrix).
__device__ __forceinline__ void gemm_split_tt(uint32_t sAhi, uint32_t sAlo,
                                              uint32_t sBhi, uint32_t sBlo,
                                              float acc[2][4][4], int lane, int m0, int n0) {
#pragma unroll
    for (int k0 = 0; k0 < 128; k0 += 16) {
        int arow = k0 + (lane & 7) + ((lane >> 4) << 3);
        int acol = ((lane >> 3) & 1) << 3;
        uint32_t aoff  = taddr(arow, m0 + acol);
        uint32_t aoff2 = taddr(arow, m0 + 16 + acol);
        uint32_t ah0[4], ah1[4], al0[4], al1[4];
        ldsm4t(ah0, sAhi + aoff);  ldsm4t(ah1, sAhi + aoff2);
        ldsm4t(al0, sAlo + aoff);  ldsm4t(al1, sAlo + aoff2);
        int brow = k0 + (lane & 7) + (((lane >> 3) & 1) << 3);
#pragma unroll
        for (int j = 0; j < 4; j++) {
            uint32_t boff = taddr(brow, n0 + j * 8);
            uint32_t bh[2], bl[2];
            ldsm2t(bh, sBhi + boff); ldsm2t(bl, sBlo + boff);
            mma16816(acc[0][j], ah0, bh); mma16816(acc[1][j], ah1, bh);
            mma16816(acc[0][j], ah0, bl); mma16816(acc[1][j], ah1, bl);
            mma16816(acc[0][j], al0, bh); mma16816(acc[1][j], al1, bh);
        }
    }
}

#define WARP_SETUP()                                                 \
    int tid = threadIdx.x;                                           \
    int lane = tid & 31, wid = tid >> 5;                             \
    int m0 = (wid & 3) * 32, n0 = (wid >> 2) * 32;                   \
    int qr = lane >> 2, qc = (lane & 3) * 2;                         \
    (void)qr; (void)qc;

#define TILE_PTRS(CS)                                                \
    extern __shared__ __align__(1024) char dsm[];                    \
    char* Ahi = dsm + OFF_AHI; char* Alo = dsm + OFF_ALO;            \
    char* Xhi = dsm + OFF_XHI; char* Xlo = dsm + OFF_XLO;            \
    uint32_t sb = smem_u32(dsm);                                     \
    uint32_t sAhi = sb + OFF_AHI, sAlo = sb + OFF_ALO;               \
    uint32_t sBhi = sb + OFF_BHI, sBlo = sb + OFF_BLO;               \
    float* ctrl = (float*)(dsm + (CS));                              \
    (void)Ahi; (void)Alo; (void)Xhi; (void)Xlo; (void)ctrl;

// ---------------- prep kernels -----------------------------------------------
__global__ void colb_kernel(const float* __restrict__ Bm) {
    int k = threadIdx.x, p = blockIdx.x;
    float s = 0.f;
    int r0 = p * 256;
    for (int r = 0; r < 256; r++) s += Bm[(r0 + r) * KM + k];
    g_colb[p * KM + k] = s;
}
__global__ void transpose_w_kernel(const float* __restrict__ W, int which) {
    float* Wt = which ? g_c3t : g_c1t;
    __shared__ float tile[32][33];
    int x0 = blockIdx.x * 32, y0 = blockIdx.y * 32;
    int tx = threadIdx.x, ty = threadIdx.y;
#pragma unroll
    for (int r = 0; r < 32; r += 8)
        tile[ty + r][tx] = W[(x0 + ty + r) * KM + y0 + tx];
    __syncthreads();
#pragma unroll
    for (int r = 0; r < 32; r += 8)
        Wt[(y0 + ty + r) * (D * D) + x0 + tx] = tile[tx][ty + r];
}
// weight image [o][ci] = W[ci][o]
__global__ void split_w_kernel(const float* __restrict__ W, int widx) {
    int p = blockIdx.x * 256 + threadIdx.x;     // 32 blocks -> 8192
    int r = p >> 6, c = (p & 63) << 1;
    store_split(WIMG(widx, 0), WIMG(widx, 1), r, c, W[c * D + r], W[(c + 1) * D + r]);
}
__global__ void split_B_kernel(const float* __restrict__ Bm) {
    int tile = blockIdx.x;                       // 64
    for (int p = threadIdx.x; p < 8192; p += 256) {
        int r = p >> 6, c = (p & 63) << 1;
        float2 v = *(const float2*)(Bm + (size_t)(tile * 128 + r) * KM + c);
        store_split(BIMG(tile, 0), BIMG(tile, 1), r, c, v.x, v.y);
    }
}
__global__ void reduce2_kernel() {
    int e = blockIdx.x * 256 + threadIdx.x;
    int b = blockIdx.y;
    float s = 0.f;
#pragma unroll
    for (int cz = 0; cz < NCHUNK; cz++)
        s += g_part[(b * NCHUNK + cz) * D * KM + e];
    g_S[b * D * KM + e] = s;
}

#define AST 132
__device__ __forceinline__ void gemm8x8(const float* __restrict__ A, const float* __restrict__ W,
                                        float (&acc)[8][8], int ty, int tx, int kdim) {
    const float* ap = A + ty * 8;
    const float* wp = W + tx * 8;
#pragma unroll 4
    for (int k = 0; k < kdim; k++) {
        float4 a0 = *(const float4*)(ap + k * AST);
        float4 a1 = *(const float4*)(ap + k * AST + 4);
        float4 w0 = *(const float4*)(wp + k * AST);
        float4 w1 = *(const float4*)(wp + k * AST + 4);
        float a[8] = {a0.x,a0.y,a0.z,a0.w,a1.x,a1.y,a1.z,a1.w};
        float w[8] = {w0.x,w0.y,w0.z,w0.w,w1.x,w1.y,w1.z,w1.w};
#pragma unroll
        for (int i = 0; i < 8; i++)
#pragma unroll
            for (int j = 0; j < 8; j++)
                acc[i][j] = fmaf(a[i], w[j], acc[i][j]);
    }
}

// score image [v][kd]: wk^T S + bk (x) colB, written split
__global__ void score_kernel(const float* __restrict__ wk, const float* __restrict__ bk) {
    extern __shared__ float sm[];
    float* As = sm;
    float* Ws = sm + D * AST;
    float* cb = Ws + D * AST;
    float* bks = cb + 128;
    int b = blockIdx.x, tid = threadIdx.x;
    if (tid < KM) {
        float s = 0.f;
        for (int p = 0; p < 32; p++) s += g_colb[p * KM + tid];
        cb[tid] = s;
        bks[tid] = bk[tid];
    }
    for (int idx = tid; idx < D * D; idx += 256) {
        As[(idx >> 7) * AST + (idx & 127)] = wk[idx];
        Ws[(idx >> 7) * AST + (idx & 127)] = g_S[b * D * KM + idx];
    }
    __syncthreads();
    int ty = tid >> 4, tx = tid & 15;
    float acc[8][8] = {};
    gemm8x8(As, Ws, acc, ty, tx, D);
    // value(i,j) at image (r=v=tx*8+j, c=kd=ty*8+i)
#pragma unroll
    for (int j = 0; j < 8; j++) {
        int r = tx * 8 + j;
        float cbv = cb[r];
#pragma unroll
        for (int i = 0; i < 8; i += 2) {
            float v0 = acc[i][j]     + bks[ty * 8 + i]     * cbv;
            float v1 = acc[i + 1][j] + bks[ty * 8 + i + 1] * cbv;
            store_split(SCIMG(b, 0), SCIMG(b, 1), r, ty * 8 + i, v0, v1);
        }
    }
}

// Yt image [o][k]: Yt[b][o][k] = sum_i S[b][i][k] W[k][i][o]
__global__ void gconv_modes_kernel(int which) {
    const float* Wt = which ? g_c3t : g_c1t;
    __shared__ float Ss[BB * D];
    int k = blockIdx.x, tid = threadIdx.x;
    for (int idx = tid; idx < BB * D; idx += 256)
        Ss[idx] = g_S[((idx >> 7) * D + (idx & 127)) * KM + k];
    __syncthreads();
    int hi = tid >> 7, o = tid & 127;
    float acc[8] = {};
    for (int i = 0; i < D; i++) {
        float w = Wt[(k * D + i) * D + o];
#pragma unroll
        for (int q = 0; q < 8; q++)
            acc[q] = fmaf(Ss[(hi * 8 + q) * D + i], w, acc[q]);
    }
    uint32_t a = taddr(o, k);
#pragma unroll
    for (int q = 0; q < 8; q++) {
        int bi = hi * 8 + q;
        __nv_bfloat16 hb = __float2bfloat16(acc[q]);
        __nv_bfloat16 lb = __float2bfloat16(acc[q] - __bfloat162float(hb));
        *(uint16_t*)(SCIMG(bi, 0) + a) = *(uint16_t*)&hb;
        *(uint16_t*)(SCIMG(bi, 1) + a) = *(uint16_t*)&lb;
    }
}

// ---------------- fc0 ---------------------------------------------------------
__global__ __launch_bounds__(NTH, 1)
void fc0_kernel(const float* __restrict__ x, const float* __restrict__ w1,
                const float* __restrict__ b1, const float* __restrict__ b2) {
    TILE_PTRS(CS_MID); WARP_SETUP();
    float* xs  = ctrl;          // 256
    float* w1s = ctrl + 256;    // 256
    float* b1s = ctrl + 512;    // 128
    float* b2s = ctrl + 640;    // 128
    int tile = blockIdx.x;
    int tok0 = tile * 128;

    cpimg(sBhi, WIMG(0, 0), tid); cpimg(sBlo, WIMG(0, 1), tid); CP_COMMIT();
    if (tid < 256) { xs[tid] = x[tok0 * 2 + tid]; w1s[tid] = w1[tid]; }
    if (tid < 128) { b1s[tid] = b1[tid]; b2s[tid] = b2[tid]; }
    __syncthreads();

    for (int p = tid; p < 128 * 64; p += NTH) {
        int r = p >> 6, c = (p & 63) << 1;
        float v0 = gelu_f(xs[2*r] * w1s[c]   + xs[2*r+1] * w1s[128+c]   + b1s[c]);
        float v1 = gelu_f(xs[2*r] * w1s[c+1] + xs[2*r+1] * w1s[128+c+1] + b1s[c+1]);
        uint32_t lw, hw = split_pack(v0, v1, lw);
        uint32_t a = taddr(r, c);
        *(uint32_t*)(Ahi + a) = hw; *(uint32_t*)(Alo + a) = lw;
    }
    CP_WAIT0(); __syncthreads();

    float acc[2][4][4] = {};
    gemm_split(sAhi, sAlo, sBhi, sBlo, acc, lane, m0, n0);

    char* oh = HIMG(tile, 0); char* ol = HIMG(tile, 1);
#pragma unroll
    for (int mt = 0; mt < 2; mt++)
#pragma unroll
        for (int j = 0; j < 4; j++) {
            int row = m0 + mt * 16 + qr, col = n0 + j * 8 + qc;
            store_split(oh, ol, row,     col, acc[mt][j][0] + b2s[col], acc[mt][j][1] + b2s[col + 1]);
            store_split(oh, ol, row + 8, col, acc[mt][j][2] + b2s[col], acc[mt][j][3] + b2s[col + 1]);
        }
}

// ---------------- reduce: S-chunk = h^T B over 512 tokens ---------------------
__global__ __launch_bounds__(NTH, 1)
void reduce_kernel() {
    TILE_PTRS(CS_MID); WARP_SETUP();
    int cz = blockIdx.x, b = blockIdx.y;
    float acc[2][4][4] = {};
    for (int sub = 0; sub < 4; sub++) {
        int t = cz * 4 + sub;
        cpimg(sAhi, HIMG(b * 64 + t, 0), tid); cpimg(sAlo, HIMG(b * 64 + t, 1), tid);
        cpimg(sBhi, BIMG(t, 0), tid);          cpimg(sBlo, BIMG(t, 1), tid);
        CP_COMMIT(); CP_WAIT0(); __syncthreads();
        gemm_split_tt(sAhi, sAlo, sBhi, sBlo, acc, lane, m0, n0);
        __syncthreads();
    }
    size_t ob = (size_t)(b * NCHUNK + cz) * D * KM;
#pragma unroll
    for (int mt = 0; mt < 2; mt++)
#pragma unroll
        for (int j = 0; j < 4; j++) {
            int row = m0 + mt * 16 + qr, col = n0 + j * 8 + qc;
            *(float2*)&g_part[ob + (size_t)row * KM + col]       = make_float2(acc[mt][j][0], acc[mt][j][1]);
            *(float2*)&g_part[ob + (size_t)(row + 8) * KM + col] = make_float2(acc[mt][j][2], acc[mt][j][3]);
        }
}

// ---------------- attention map (3 chained GEMMs) ----------------------------
__global__ __launch_bounds__(NTH, 1)
void attn_map_kernel(int wbase, const float* __restrict__ f1b, const float* __restrict__ f2b) {
    TILE_PTRS(CS_BIG); WARP_SETUP();
    uint32_t sXhi = sb + OFF_XHI, sXlo = sb + OFF_XLO;
    int b = blockIdx.x >> 6;
    int tile = blockIdx.x;

    if (tid < 128) { ctrl[tid] = f1b[tid]; ctrl[128 + tid] = f2b[tid]; }
    cpimg(sAhi, BIMG(tile & 63, 0), tid); cpimg(sAlo, BIMG(tile & 63, 1), tid);
    cpimg(sBhi, SCIMG(b, 0), tid);        cpimg(sBlo, SCIMG(b, 1), tid);
    cpimg(sXhi, HIMG(tile, 0), tid);      cpimg(sXlo, HIMG(tile, 1), tid);
    CP_COMMIT(); CP_WAIT0(); __syncthreads();

    float acc[2][4][4] = {};
    gemm_split(sAhi, sAlo, sBhi, sBlo, acc, lane, m0, n0);   // attn = Btile @ score^T
    __syncthreads();

    cpimg(sBhi, WIMG(wbase, 0), tid); cpimg(sBlo, WIMG(wbase, 1), tid); CP_COMMIT();
    // ep1: xt = gelu(attn) + h -> A (operand), X (residual keep)
#pragma unroll
    for (int mt = 0; mt < 2; mt++)
#pragma unroll
        for (int j = 0; j < 4; j++) {
            int row = m0 + mt * 16 + qr, col = n0 + j * 8 + qc;
#pragma unroll
            for (int h = 0; h < 2; h++) {
                int r = row + h * 8;
                uint32_t a = taddr(r, col);
                float2 hh = unpack_split(*(uint32_t*)(Xhi + a), *(uint32_t*)(Xlo + a));
                float x0 = gelu_f(acc[mt][j][2*h])   + hh.x;
                float x1 = gelu_f(acc[mt][j][2*h+1]) + hh.y;
                uint32_t lw, hw = split_pack(x0, x1, lw);
                *(uint32_t*)(Ahi + a) = hw; *(uint32_t*)(Alo + a) = lw;
                *(uint32_t*)(Xhi + a) = hw; *(uint32_t*)(Xlo + a) = lw;
            }
        }
    CP_WAIT0(); __syncthreads();

    float acc2[2][4][4] = {};
    gemm_split(sAhi, sAlo, sBhi, sBlo, acc2, lane, m0, n0);  // u = xt @ f1w
    __syncthreads();

    cpimg(sBhi, WIMG(wbase + 1, 0), tid); cpimg(sBlo, WIMG(wbase + 1, 1), tid); CP_COMMIT();
    // ep2: g = gelu(u + f1b) -> A
#pragma unroll
    for (int mt = 0; mt < 2; mt++)
#pragma unroll
        for (int j = 0; j < 4; j++) {
            int row = m0 + mt * 16 + qr, col = n0 + j * 8 + qc;
#pragma unroll
            for (int h = 0; h < 2; h++) {
                int r = row + h * 8;
                float g0 = gelu_f(acc2[mt][j][2*h]   + ctrl[col]);
                float g1 = gelu_f(acc2[mt][j][2*h+1] + ctrl[col + 1]);
                uint32_t lw, hw = split_pack(g0, g1, lw);
                uint32_t a = taddr(r, col);
                *(uint32_t*)(Ahi + a) = hw; *(uint32_t*)(Alo + a) = lw;
            }
        }
    CP_WAIT0(); __syncthreads();

    float acc3[2][4][4] = {};
    gemm_split(sAhi, sAlo, sBhi, sBlo, acc3, lane, m0, n0);  // r = g @ f2w

    char* oh = HIMG(tile, 0); char* ol = HIMG(tile, 1);
#pragma unroll
    for (int mt = 0; mt < 2; mt++)
#pragma unroll
        for (int j = 0; j < 4; j++) {
            int row = m0 + mt * 16 + qr, col = n0 + j * 8 + qc;
#pragma unroll
            for (int h = 0; h < 2; h++) {
                int r = row + h * 8;
                uint32_t a = taddr(r, col);
                float2 xt = unpack_split(*(uint32_t*)(Xhi + a), *(uint32_t*)(Xlo + a));
                store_split(oh, ol, r, col,
                            xt.x + acc3[mt][j][2*h]   + ctrl[128 + col],
                            xt.y + acc3[mt][j][2*h+1] + ctrl[128 + col + 1]);
            }
        }
}

// ---------------- gconv map (2 GEMMs accumulated) ----------------------------
__global__ __launch_bounds__(NTH, 1)
void gconv_map_kernel(int widx, const float* __restrict__ wb, int act) {
    TILE_PTRS(CS_MID); WARP_SETUP();
    int b = blockIdx.x >> 6;
    int tile = blockIdx.x;

    if (tid < 128) ctrl[tid] = wb[tid];
    cpimg(sAhi, BIMG(tile & 63, 0), tid); cpimg(sAlo, BIMG(tile & 63, 1), tid);
    cpimg(sBhi, SCIMG(b, 0), tid);        cpimg(sBlo, SCIMG(b, 1), tid);   // Yt image
    CP_COMMIT(); CP_WAIT0(); __syncthreads();

    float acc[2][4][4] = {};
    gemm_split(sAhi, sAlo, sBhi, sBlo, acc, lane, m0, n0);   // x1 = Btile @ Yt^T
    __syncthreads();

    cpimg(sAhi, HIMG(tile, 0), tid); cpimg(sAlo, HIMG(tile, 1), tid);
    cpimg(sBhi, WIMG(widx, 0), tid); cpimg(sBlo, WIMG(widx, 1), tid);
    CP_COMMIT(); CP_WAIT0(); __syncthreads();
    gemm_split(sAhi, sAlo, sBhi, sBlo, acc, lane, m0, n0);   // += h @ W

    char* oh = HIMG(tile, 0); char* ol = HIMG(tile, 1);
#pragma unroll
    for (int mt = 0; mt < 2; mt++)
#pragma unroll
        for (int j = 0; j < 4; j++) {
            int row = m0 + mt * 16 + qr, col = n0 + j * 8 + qc;
#pragma unroll
            for (int h = 0; h < 2; h++) {
                int r = row + h * 8;
                uint32_t a = taddr(r, col);
                float2 hh = unpack_split(*(uint32_t*)(Ahi + a), *(uint32_t*)(Alo + a));
                float z0 = acc[mt][j][2*h]   + ctrl[col];
                float z1 = acc[mt][j][2*h+1] + ctrl[col + 1];
                if (act) { z0 = gelu_f(z0); z1 = gelu_f(z1); }
                store_split(oh, ol, r, col, hh.x + z0, hh.y + z1);
            }
        }
}

// ---------------- head --------------------------------------------------------
__global__ __launch_bounds__(NTH, 1)
void head_kernel(const float* __restrict__ fc1b, const float* __restrict__ fc2w,
                 const float* __restrict__ fc2b, float* __restrict__ out) {
    TILE_PTRS(CS_MID); WARP_SETUP();
    int tile = blockIdx.x;
    size_t tok0 = (size_t)tile * 128;
    int wn = wid >> 2;

    if (tid < 128) { ctrl[tid] = fc1b[tid]; ctrl[128 + tid] = fc2w[tid]; }
    float* partial = ctrl + 256;   // [4][128]
    cpimg(sAhi, HIMG(tile, 0), tid); cpimg(sAlo, HIMG(tile, 1), tid);
    cpimg(sBhi, WIMG(7, 0), tid);    cpimg(sBlo, WIMG(7, 1), tid);
    CP_COMMIT(); CP_WAIT0(); __syncthreads();

    float acc[2][4][4] = {};
    gemm_split(sAhi, sAlo, sBhi, sBlo, acc, lane, m0, n0);

    float s[2][2] = {};
#pragma unroll
    for (int mt = 0; mt < 2; mt++)
#pragma unroll
        for (int j = 0; j < 4; j++) {
            int col = n0 + j * 8 + qc;
            s[mt][0] += gelu_f(acc[mt][j][0] + ctrl[col])     * ctrl[128 + col]
                      + gelu_f(acc[mt][j][1] + ctrl[col + 1]) * ctrl[128 + col + 1];
            s[mt][1] += gelu_f(acc[mt][j][2] + ctrl[col])     * ctrl[128 + col]
                      + gelu_f(acc[mt][j][3] + ctrl[col + 1]) * ctrl[128 + col + 1];
        }
#pragma unroll
    for (int mt = 0; mt < 2; mt++)
#pragma unroll
        for (int h = 0; h < 2; h++) {
            s[mt][h] += __shfl_xor_sync(0xffffffffu, s[mt][h], 1);
            s[mt][h] += __shfl_xor_sync(0xffffffffu, s[mt][h], 2);
        }
    if ((lane & 3) == 0) {
#pragma unroll
        for (int mt = 0; mt < 2; mt++) {
            partial[wn * 128 + m0 + mt * 16 + qr]     = s[mt][0];
            partial[wn * 128 + m0 + mt * 16 + qr + 8] = s[mt][1];
        }
    }
    __syncthreads();
    if (tid < 128)
        out[tok0 + tid] = partial[tid] + partial[128 + tid] + partial[256 + tid]
                        + partial[384 + tid] + fc2b[0];
}

// ---------------- launch ------------------------------------------------------
extern "C" void kernel_launch(void* const* d_in, const int* in_sizes, int n_in,
                              void* d_out, int out_size) {
    const float* x      = (const float*)d_in[0];
    const float* Bm     = (const float*)d_in[1];
    const float* fc0_w1 = (const float*)d_in[2];
    const float* fc0_b1 = (const float*)d_in[3];
    const float* fc0_w2 = (const float*)d_in[4];
    const float* fc0_b2 = (const float*)d_in[5];
    const float* a0_wk  = (const float*)d_in[6];
    const float* a0_bk  = (const float*)d_in[7];
    const float* a0_f1w = (const float*)d_in[8];
    const float* a0_f1b = (const float*)d_in[9];
    const float* a0_f2w = (const float*)d_in[10];
    const float* a0_f2b = (const float*)d_in[11];
    const float* c1_w   = (const float*)d_in[12];
    const float* w1_w   = (const float*)d_in[13];
    const float* w1_b   = (const float*)d_in[14];
    const float* a2_wk  = (const float*)d_in[15];
    const float* a2_bk  = (const float*)d_in[16];
    const float* a2_f1w = (const float*)d_in[17];
    const float* a2_f1b = (const float*)d_in[18];
    const float* a2_f2w = (const float*)d_in[19];
    const float* a2_f2b = (const float*)d_in[20];
    const float* c3_w   = (const float*)d_in[21];
    const float* w3_w   = (const float*)d_in[22];
    const float* w3_b   = (const float*)d_in[23];
    const float* fc1_w  = (const float*)d_in[24];
    const float* fc1_b  = (const float*)d_in[25];
    const float* fc2_w  = (const float*)d_in[26];
    const float* fc2_b  = (const float*)d_in[27];
    float* out = (float*)d_out;

    const int SM2 = (2 * D * AST + 1024) * sizeof(float);
    cudaFuncSetAttribute((const void*)fc0_kernel,       cudaFuncAttributeMaxDynamicSharedMemorySize, SM_MID);
    cudaFuncSetAttribute((const void*)reduce_kernel,    cudaFuncAttributeMaxDynamicSharedMemorySize, SM_MID);
    cudaFuncSetAttribute((const void*)attn_map_kernel,  cudaFuncAttributeMaxDynamicSharedMemorySize, SM_BIG);
    cudaFuncSetAttribute((const void*)gconv_map_kernel, cudaFuncAttributeMaxDynamicSharedMemorySize, SM_MID);
    cudaFuncSetAttribute((const void*)head_kernel,      cudaFuncAttributeMaxDynamicSharedMemorySize, SM_MID);
    cudaFuncSetAttribute((const void*)score_kernel,     cudaFuncAttributeMaxDynamicSharedMemorySize, SM2);

    colb_kernel<<<32, 128>>>(Bm);
    transpose_w_kernel<<<dim3(512, 4), dim3(32, 8)>>>(c1_w, 0);
    transpose_w_kernel<<<dim3(512, 4), dim3(32, 8)>>>(c3_w, 1);
    split_B_kernel<<<64, 256>>>(Bm);
    split_w_kernel<<<32, 256>>>(fc0_w2, 0);
    split_w_kernel<<<32, 256>>>(a0_f1w, 1);
    split_w_kernel<<<32, 256>>>(a0_f2w, 2);
    split_w_kernel<<<32, 256>>>(w1_w,   3);
    split_w_kernel<<<32, 256>>>(a2_f1w, 4);
    split_w_kernel<<<32, 256>>>(a2_f2w, 5);
    split_w_kernel<<<32, 256>>>(w3_w,   6);
    split_w_kernel<<<32, 256>>>(fc1_w,  7);

    fc0_kernel<<<NTILES, NTH, SM_MID>>>(x, fc0_w1, fc0_b1, fc0_b2);

    reduce_kernel<<<dim3(NCHUNK, BB), NTH, SM_MID>>>();
    reduce2_kernel<<<dim3(64, BB), 256>>>();
    score_kernel<<<BB, 256, SM2>>>(a0_wk, a0_bk);
    attn_map_kernel<<<NTILES, NTH, SM_BIG>>>(1, a0_f1b, a0_f2b);

    reduce_kernel<<<dim3(NCHUNK, BB), NTH, SM_MID>>>();
    reduce2_kernel<<<dim3(64, BB), 256>>>();
    gconv_modes_kernel<<<KM, 256>>>(0);
    gconv_map_kernel<<<NTILES, NTH, SM_MID>>>(3, w1_b, 1);

    reduce_kernel<<<dim3(NCHUNK, BB), NTH, SM_MID>>>();
    reduce2_kernel<<<dim3(64, BB), 256>>>();
    score_kernel<<<BB, 256, SM2>>>(a2_wk, a2_bk);
    attn_map_kernel<<<NTILES, NTH, SM_BIG>>>(4, a2_f1b, a2_f2b);

    reduce_kernel<<<dim3(NCHUNK, BB), NTH, SM_MID>>>();
    reduce2_kernel<<<dim3(64, BB), 256>>>();
    gconv_modes_kernel<<<KM, 256>>>(1);
    gconv_map_kernel<<<NTILES, NTH, SM_MID>>>(6, w3_b, 0);

    head_kernel<<<NTILES, NTH, SM_MID>>>(fc1_b, fc2_w, fc2_b, out);
}

// round 10
// speedup vs baseline: 2.6299x; 1.0187x over previous
#include <cuda_runtime.h>
#include <cuda_bf16.h>
#include <math.h>
#include <cstdint>

#define D     128
#define KM    128
#define NTOK  8192
#define BB    16
#define NCHUNK 16
#define NTILES 1024
#define NTH   512
#define IMGB  32768            // one 128x128 bf16 tile image (two 16KB col-half blocks)
#define HB    16384

// smem slots
#define OFF_AHI 0
#define OFF_ALO 32768
#define OFF_BHI 65536
#define OFF_BLO 98304
#define OFF_XHI 131072
#define OFF_XLO 163840
#define CS_MID  131072
#define CS_BIG  196608
#define SM_MID  (CS_MID + 4096)   // 135168
#define SM_BIG  (CS_BIG + 4096)   // 200704

// ---------------- global scratch ---------------------------------------------
__device__ __align__(16) char g_himg [(size_t)NTILES*2*IMGB];
__device__ __align__(16) char g_Bimg [64*2*IMGB];
__device__ __align__(16) char g_wimg [8*2*IMGB];
__device__ __align__(16) char g_scimg[BB*2*IMGB];
__device__ float g_part[BB*NCHUNK*D*KM];
__device__ float g_S   [BB*D*KM];
__device__ float g_c1t [KM*D*D];
__device__ float g_c3t [KM*D*D];
__device__ float g_colb[32*KM];

#define HIMG(t,hl)  (g_himg  + ((size_t)(t)*2 + (hl))*IMGB)
#define BIMG(t,hl)  (g_Bimg  + ((size_t)(t)*2 + (hl))*IMGB)
#define WIMG(w,hl)  (g_wimg  + ((size_t)(w)*2 + (hl))*IMGB)
#define SCIMG(b,hl) (g_scimg + ((size_t)(b)*2 + (hl))*IMGB)
// weight idx: 0 fc0_w2, 1 a0_f1w, 2 a0_f2w, 3 w1_w, 4 a2_f1w, 5 a2_f2w, 6 w3_w, 7 fc1_w

// ---------------- helpers ----------------------------------------------------
__device__ __forceinline__ uint32_t smem_u32(const void* p) {
    uint32_t a;
    asm("{ .reg .u64 t; cvta.to.shared.u64 t, %1; cvt.u32.u64 %0, t; }" : "=r"(a) : "l"(p));
    return a;
}
__device__ __forceinline__ float gelu_f(float x) {
    return 0.5f * x * (1.0f + erff(x * 0.7071067811865475f));
}
// k-blocked image: col-half block (16KB) + 128B rows, XOR swizzle within row
__device__ __forceinline__ uint32_t taddr(int r, int c) {
    return ((uint32_t)(c >> 6) << 14) + ((uint32_t)r << 7)
         + (uint32_t)((((c & 63) << 1)) ^ ((r & 7) << 4));
}
__device__ __forceinline__ uint32_t split_pack(float x0, float x1, uint32_t& lop) {
    __nv_bfloat16 h0 = __float2bfloat16(x0);
    __nv_bfloat16 h1 = __float2bfloat16(x1);
    __nv_bfloat16 l0 = __float2bfloat16(x0 - __bfloat162float(h0));
    __nv_bfloat16 l1 = __float2bfloat16(x1 - __bfloat162float(h1));
    __nv_bfloat162 hp; hp.x = h0; hp.y = h1;
    __nv_bfloat162 lp; lp.x = l0; lp.y = l1;
    lop = *(uint32_t*)&lp;
    return *(uint32_t*)&hp;
}
__device__ __forceinline__ float2 unpack_split(uint32_t hw, uint32_t lw) {
    __nv_bfloat162 hp = *(__nv_bfloat162*)&hw;
    __nv_bfloat162 lp = *(__nv_bfloat162*)&lw;
    return make_float2(__bfloat162float(hp.x) + __bfloat162float(lp.x),
                       __bfloat162float(hp.y) + __bfloat162float(lp.y));
}
__device__ __forceinline__ void store_split(char* ihi, char* ilo, int r, int c,
                                            float v0, float v1) {
    uint32_t lw, hw = split_pack(v0, v1, lw);
    uint32_t a = taddr(r, c);
    *(uint32_t*)(ihi + a) = hw; *(uint32_t*)(ilo + a) = lw;
}

// cp.async
__device__ __forceinline__ void cp16(uint32_t s, const void* g) {
    asm volatile("cp.async.cg.shared.global [%0], [%1], 16;" :: "r"(s), "l"(g) : "memory");
}
#define CP_COMMIT() asm volatile("cp.async.commit_group;" ::: "memory")
#define CP_WAIT0()  asm volatile("cp.async.wait_group 0;" ::: "memory")
#define CP_WAIT1()  asm volatile("cp.async.wait_group 1;" ::: "memory")
// copy one COLUMN-half block (16KB): cols [half*64, half*64+64), all rows
__device__ __forceinline__ void cpimg_h(uint32_t sdst, const char* g, int half, int tid) {
    uint32_t off = (uint32_t)half * HB;
    for (int i = tid; i < 1024; i += NTH) cp16(sdst + off + i * 16, g + off + i * 16);
}
// copy one ROW-half (rows [half*64, half*64+64), ALL columns) = 8KB of each block
__device__ __forceinline__ void cpimg_rh(uint32_t sdst, const char* g, int half, int tid) {
    uint32_t off = (uint32_t)half * 8192;
    for (int i = tid; i < 512; i += NTH) {
        cp16(sdst + off + i * 16,      g + off + i * 16);        // block 0 rows
        cp16(sdst + HB + off + i * 16, g + HB + off + i * 16);   // block 1 rows
    }
}
__device__ __forceinline__ void cpimg(uint32_t sdst, const char* g, int tid) {
    for (int i = tid; i < 2048; i += NTH) cp16(sdst + i * 16, g + i * 16);
}

// ldmatrix / mma
__device__ __forceinline__ void ldsm4(uint32_t a[4], uint32_t addr) {
    asm volatile("ldmatrix.sync.aligned.m8n8.x4.shared.b16 {%0,%1,%2,%3}, [%4];"
        : "=r"(a[0]), "=r"(a[1]), "=r"(a[2]), "=r"(a[3]) : "r"(addr));
}
__device__ __forceinline__ void ldsm2(uint32_t b[2], uint32_t addr) {
    asm volatile("ldmatrix.sync.aligned.m8n8.x2.shared.b16 {%0,%1}, [%2];"
        : "=r"(b[0]), "=r"(b[1]) : "r"(addr));
}
__device__ __forceinline__ void ldsm4t(uint32_t a[4], uint32_t addr) {
    asm volatile("ldmatrix.sync.aligned.m8n8.x4.trans.shared.b16 {%0,%1,%2,%3}, [%4];"
        : "=r"(a[0]), "=r"(a[1]), "=r"(a[2]), "=r"(a[3]) : "r"(addr));
}
__device__ __forceinline__ void ldsm2t(uint32_t b[2], uint32_t addr) {
    asm volatile("ldmatrix.sync.aligned.m8n8.x2.trans.shared.b16 {%0,%1}, [%2];"
        : "=r"(b[0]), "=r"(b[1]) : "r"(addr));
}
__device__ __forceinline__ void mma16816(float c[4], const uint32_t a[4], const uint32_t b[2]) {
    asm volatile("mma.sync.aligned.m16n8k16.row.col.f32.bf16.bf16.f32 "
        "{%0,%1,%2,%3}, {%4,%5,%6,%7}, {%8,%9}, {%0,%1,%2,%3};"
        : "+f"(c[0]), "+f"(c[1]), "+f"(c[2]), "+f"(c[3])
        : "r"(a[0]), "r"(a[1]), "r"(a[2]), "r"(a[3]), "r"(b[0]), "r"(b[1]));
}

// one k-half (64 cols) of C[m][n] += A[m][k] B[n][k]
__device__ __forceinline__ void gemm_h(uint32_t sAhi, uint32_t sAlo,
                                       uint32_t sBhi, uint32_t sBlo,
                                       float acc[2][4][4], int lane, int m0, int n0, int kbeg) {
#pragma unroll
    for (int k0 = kbeg; k0 < kbeg + 64; k0 += 16) {
        uint32_t aoff  = taddr(m0 + (lane & 15), k0 + ((lane >> 4) << 3));
        uint32_t aoff2 = taddr(m0 + 16 + (lane & 15), k0 + ((lane >> 4) << 3));
        uint32_t ah0[4], ah1[4], al0[4], al1[4];
        ldsm4(ah0, sAhi + aoff);  ldsm4(ah1, sAhi + aoff2);
        ldsm4(al0, sAlo + aoff);  ldsm4(al1, sAlo + aoff2);
#pragma unroll
        for (int j = 0; j < 4; j++) {
            uint32_t boff = taddr(n0 + j * 8 + (lane & 7), k0 + ((lane >> 3) & 1) * 8);
            uint32_t bh[2], bl[2];
            ldsm2(bh, sBhi + boff); ldsm2(bl, sBlo + boff);
            mma16816(acc[0][j], ah0, bh); mma16816(acc[1][j], ah1, bh);
            mma16816(acc[0][j], ah0, bl); mma16816(acc[1][j], ah1, bl);
            mma16816(acc[0][j], al0, bh); mma16816(acc[1][j], al1, bh);
        }
    }
}

// one k-half (64 ROWS) of C[m][n] += A[t][m] B[t][n] (t-major images, trans ldmatrix)
__device__ __forceinline__ void gemm_tt_h(uint32_t sAhi, uint32_t sAlo,
                                          uint32_t sBhi, uint32_t sBlo,
                                          float acc[2][4][4], int lane, int m0, int n0, int kbeg) {
#pragma unroll
    for (int k0 = kbeg; k0 < kbeg + 64; k0 += 16) {
        int arow = k0 + (lane & 7) + ((lane >> 4) << 3);
        int acol = ((lane >> 3) & 1) << 3;
        uint32_t aoff  = taddr(arow, m0 + acol);
        uint32_t aoff2 = taddr(arow, m0 + 16 + acol);
        uint32_t ah0[4], ah1[4], al0[4], al1[4];
        ldsm4t(ah0, sAhi + aoff);  ldsm4t(ah1, sAhi + aoff2);
        ldsm4t(al0, sAlo + aoff);  ldsm4t(al1, sAlo + aoff2);
        int brow = k0 + (lane & 7) + (((lane >> 3) & 1) << 3);
#pragma unroll
        for (int j = 0; j < 4; j++) {
            uint32_t boff = taddr(brow, n0 + j * 8);
            uint32_t bh[2], bl[2];
            ldsm2t(bh, sBhi + boff); ldsm2t(bl, sBlo + boff);
            mma16816(acc[0][j], ah0, bh); mma16816(acc[1][j], ah1, bh);
            mma16816(acc[0][j], ah0, bl); mma16816(acc[1][j], ah1, bl);
            mma16816(acc[0][j], al0, bh); mma16816(acc[1][j], al1, bh);
        }
    }
}

#define WARP_SETUP()                                                 \
    int tid = threadIdx.x;                                           \
    int lane = tid & 31, wid = tid >> 5;                             \
    int m0 = (wid & 3) * 32, n0 = (wid >> 2) * 32;                   \
    int qr = lane >> 2, qc = (lane & 3) * 2;                         \
    (void)qr; (void)qc;

#define TILE_PTRS(CS)                                                \
    extern __shared__ __align__(1024) char dsm[];                    \
    char* Ahi = dsm + OFF_AHI; char* Alo = dsm + OFF_ALO;            \
    char* Xhi = dsm + OFF_XHI; char* Xlo = dsm + OFF_XLO;            \
    uint32_t sb = smem_u32(dsm);                                     \
    uint32_t sAhi = sb + OFF_AHI, sAlo = sb + OFF_ALO;               \
    uint32_t sBhi = sb + OFF_BHI, sBlo = sb + OFF_BLO;               \
    float* ctrl = (float*)(dsm + (CS));                              \
    (void)Ahi; (void)Alo; (void)Xhi; (void)Xlo; (void)ctrl;

// ---------------- prep kernels -----------------------------------------------
__global__ void colb_kernel(const float* __restrict__ Bm) {
    int k = threadIdx.x, p = blockIdx.x;
    float s = 0.f;
    int r0 = p * 256;
    for (int r = 0; r < 256; r++) s += Bm[(r0 + r) * KM + k];
    g_colb[p * KM + k] = s;
}
__global__ void transpose_w_kernel(const float* __restrict__ W, int which) {
    float* Wt = which ? g_c3t : g_c1t;
    __shared__ float tile[32][33];
    int x0 = blockIdx.x * 32, y0 = blockIdx.y * 32;
    int tx = threadIdx.x, ty = threadIdx.y;
#pragma unroll
    for (int r = 0; r < 32; r += 8)
        tile[ty + r][tx] = W[(x0 + ty + r) * KM + y0 + tx];
    __syncthreads();
#pragma unroll
    for (int r = 0; r < 32; r += 8)
        Wt[(y0 + ty + r) * (D * D) + x0 + tx] = tile[tx][ty + r];
}
__global__ void split_w_kernel(const float* __restrict__ W, int widx) {
    int p = blockIdx.x * 256 + threadIdx.x;
    int r = p >> 6, c = (p & 63) << 1;
    store_split(WIMG(widx, 0), WIMG(widx, 1), r, c, W[c * D + r], W[(c + 1) * D + r]);
}
__global__ void split_B_kernel(const float* __restrict__ Bm) {
    int tile = blockIdx.x;
    for (int p = threadIdx.x; p < 8192; p += 256) {
        int r = p >> 6, c = (p & 63) << 1;
        float2 v = *(const float2*)(Bm + (size_t)(tile * 128 + r) * KM + c);
        store_split(BIMG(tile, 0), BIMG(tile, 1), r, c, v.x, v.y);
    }
}
__global__ void reduce2_kernel() {
    int e = blockIdx.x * 256 + threadIdx.x;
    int b = blockIdx.y;
    float s = 0.f;
#pragma unroll
    for (int cz = 0; cz < NCHUNK; cz++)
        s += g_part[(b * NCHUNK + cz) * D * KM + e];
    g_S[b * D * KM + e] = s;
}

#define AST 132
__device__ __forceinline__ void gemm8x8(const float* __restrict__ A, const float* __restrict__ W,
                                        float (&acc)[8][8], int ty, int tx, int kdim) {
    const float* ap = A + ty * 8;
    const float* wp = W + tx * 8;
#pragma unroll 4
    for (int k = 0; k < kdim; k++) {
        float4 a0 = *(const float4*)(ap + k * AST);
        float4 a1 = *(const float4*)(ap + k * AST + 4);
        float4 w0 = *(const float4*)(wp + k * AST);
        float4 w1 = *(const float4*)(wp + k * AST + 4);
        float a[8] = {a0.x,a0.y,a0.z,a0.w,a1.x,a1.y,a1.z,a1.w};
        float w[8] = {w0.x,w0.y,w0.z,w0.w,w1.x,w1.y,w1.z,w1.w};
#pragma unroll
        for (int i = 0; i < 8; i++)
#pragma unroll
            for (int j = 0; j < 8; j++)
                acc[i][j] = fmaf(a[i], w[j], acc[i][j]);
    }
}

__global__ void score_kernel(const float* __restrict__ wk, const float* __restrict__ bk) {
    extern __shared__ float sm[];
    float* As = sm;
    float* Ws = sm + D * AST;
    float* cb = Ws + D * AST;
    float* bks = cb + 128;
    int b = blockIdx.x, tid = threadIdx.x;
    if (tid < KM) {
        float s = 0.f;
        for (int p = 0; p < 32; p++) s += g_colb[p * KM + tid];
        cb[tid] = s;
        bks[tid] = bk[tid];
    }
    for (int idx = tid; idx < D * D; idx += 256) {
        As[(idx >> 7) * AST + (idx & 127)] = wk[idx];
        Ws[(idx >> 7) * AST + (idx & 127)] = g_S[b * D * KM + idx];
    }
    __syncthreads();
    int ty = tid >> 4, tx = tid & 15;
    float acc[8][8] = {};
    gemm8x8(As, Ws, acc, ty, tx, D);
#pragma unroll
    for (int j = 0; j < 8; j++) {
        int r = tx * 8 + j;
        float cbv = cb[r];
#pragma unroll
        for (int i = 0; i < 8; i += 2) {
            float v0 = acc[i][j]     + bks[ty * 8 + i]     * cbv;
            float v1 = acc[i + 1][j] + bks[ty * 8 + i + 1] * cbv;
            store_split(SCIMG(b, 0), SCIMG(b, 1), r, ty * 8 + i, v0, v1);
        }
    }
}

__global__ void gconv_modes_kernel(int which) {
    const float* Wt = which ? g_c3t : g_c1t;
    __shared__ float Ss[BB * D];
    int k = blockIdx.x, tid = threadIdx.x;
    for (int idx = tid; idx < BB * D; idx += 256)
        Ss[idx] = g_S[((idx >> 7) * D + (idx & 127)) * KM + k];
    __syncthreads();
    int hi = tid >> 7, o = tid & 127;
    float acc[8] = {};
    for (int i = 0; i < D; i++) {
        float w = Wt[(k * D + i) * D + o];
#pragma unroll
        for (int q = 0; q < 8; q++)
            acc[q] = fmaf(Ss[(hi * 8 + q) * D + i], w, acc[q]);
    }
    uint32_t a = taddr(o, k);
#pragma unroll
    for (int q = 0; q < 8; q++) {
        int bi = hi * 8 + q;
        __nv_bfloat16 hb = __float2bfloat16(acc[q]);
        __nv_bfloat16 lb = __float2bfloat16(acc[q] - __bfloat162float(hb));
        *(uint16_t*)(SCIMG(bi, 0) + a) = *(uint16_t*)&hb;
        *(uint16_t*)(SCIMG(bi, 1) + a) = *(uint16_t*)&lb;
    }
}

// ---------------- fc0 ---------------------------------------------------------
__global__ __launch_bounds__(NTH, 1)
void fc0_kernel(const float* __restrict__ x, const float* __restrict__ w1,
                const float* __restrict__ b1, const float* __restrict__ b2) {
    TILE_PTRS(CS_MID); WARP_SETUP();
    float* xs  = ctrl;
    float* w1s = ctrl + 256;
    float* b1s = ctrl + 512;
    float* b2s = ctrl + 640;
    int tile = blockIdx.x;
    int tok0 = tile * 128;

    cpimg_h(sBhi, WIMG(0, 0), 0, tid); cpimg_h(sBlo, WIMG(0, 1), 0, tid); CP_COMMIT();
    cpimg_h(sBhi, WIMG(0, 0), 1, tid); cpimg_h(sBlo, WIMG(0, 1), 1, tid); CP_COMMIT();
    if (tid < 256) { xs[tid] = x[tok0 * 2 + tid]; w1s[tid] = w1[tid]; }
    if (tid < 128) { b1s[tid] = b1[tid]; b2s[tid] = b2[tid]; }
    __syncthreads();

    for (int p = tid; p < 128 * 64; p += NTH) {
        int r = p >> 6, c = (p & 63) << 1;
        float v0 = gelu_f(xs[2*r] * w1s[c]   + xs[2*r+1] * w1s[128+c]   + b1s[c]);
        float v1 = gelu_f(xs[2*r] * w1s[c+1] + xs[2*r+1] * w1s[128+c+1] + b1s[c+1]);
        uint32_t lw, hw = split_pack(v0, v1, lw);
        uint32_t a = taddr(r, c);
        *(uint32_t*)(Ahi + a) = hw; *(uint32_t*)(Alo + a) = lw;
    }
    CP_WAIT1(); __syncthreads();

    float acc[2][4][4] = {};
    gemm_h(sAhi, sAlo, sBhi, sBlo, acc, lane, m0, n0, 0);
    CP_WAIT0(); __syncthreads();
    gemm_h(sAhi, sAlo, sBhi, sBlo, acc, lane, m0, n0, 64);

    char* oh = HIMG(tile, 0); char* ol = HIMG(tile, 1);
#pragma unroll
    for (int mt = 0; mt < 2; mt++)
#pragma unroll
        for (int j = 0; j < 4; j++) {
            int row = m0 + mt * 16 + qr, col = n0 + j * 8 + qc;
            store_split(oh, ol, row,     col, acc[mt][j][0] + b2s[col], acc[mt][j][1] + b2s[col + 1]);
            store_split(oh, ol, row + 8, col, acc[mt][j][2] + b2s[col], acc[mt][j][3] + b2s[col + 1]);
        }
}

// ---------------- reduce: pipelined 4-sub GEMM chain (ROW-half staging) ------
__global__ __launch_bounds__(NTH, 1)
void reduce_kernel() {
    TILE_PTRS(CS_MID); WARP_SETUP();
    int cz = blockIdx.x, b = blockIdx.y;
    float acc[2][4][4] = {};
    int t0 = cz * 4;
    // prologue: row-halves of sub 0
    cpimg_rh(sAhi, HIMG(b * 64 + t0, 0), 0, tid); cpimg_rh(sAlo, HIMG(b * 64 + t0, 1), 0, tid);
    cpimg_rh(sBhi, BIMG(t0, 0), 0, tid);          cpimg_rh(sBlo, BIMG(t0, 1), 0, tid);
    CP_COMMIT();
    cpimg_rh(sAhi, HIMG(b * 64 + t0, 0), 1, tid); cpimg_rh(sAlo, HIMG(b * 64 + t0, 1), 1, tid);
    cpimg_rh(sBhi, BIMG(t0, 0), 1, tid);          cpimg_rh(sBlo, BIMG(t0, 1), 1, tid);
    CP_COMMIT();
    for (int s = 0; s < 4; s++) {
        int tn = t0 + s + 1;
        CP_WAIT1(); __syncthreads();
        gemm_tt_h(sAhi, sAlo, sBhi, sBlo, acc, lane, m0, n0, 0);   // rows 0-63
        __syncthreads();
        if (s < 3) {
            cpimg_rh(sAhi, HIMG(b * 64 + tn, 0), 0, tid); cpimg_rh(sAlo, HIMG(b * 64 + tn, 1), 0, tid);
            cpimg_rh(sBhi, BIMG(tn, 0), 0, tid);          cpimg_rh(sBlo, BIMG(tn, 1), 0, tid);
            CP_COMMIT();
            CP_WAIT1();
        } else {
            CP_WAIT0();
        }
        __syncthreads();
        gemm_tt_h(sAhi, sAlo, sBhi, sBlo, acc, lane, m0, n0, 64);  // rows 64-127
        __syncthreads();
        if (s < 3) {
            cpimg_rh(sAhi, HIMG(b * 64 + tn, 0), 1, tid); cpimg_rh(sAlo, HIMG(b * 64 + tn, 1), 1, tid);
            cpimg_rh(sBhi, BIMG(tn, 0), 1, tid);          cpimg_rh(sBlo, BIMG(tn, 1), 1, tid);
            CP_COMMIT();
        }
    }
    size_t ob = (size_t)(b * NCHUNK + cz) * D * KM;
#pragma unroll
    for (int mt = 0; mt < 2; mt++)
#pragma unroll
        for (int j = 0; j < 4; j++) {
            int row = m0 + mt * 16 + qr, col = n0 + j * 8 + qc;
            *(float2*)&g_part[ob + (size_t)row * KM + col]       = make_float2(acc[mt][j][0], acc[mt][j][1]);
            *(float2*)&g_part[ob + (size_t)(row + 8) * KM + col] = make_float2(acc[mt][j][2], acc[mt][j][3]);
        }
}

// ---------------- attention map (3 chained GEMMs, pipelined) -----------------
__global__ __launch_bounds__(NTH, 1)
void attn_map_kernel(int wbase, const float* __restrict__ f1b, const float* __restrict__ f2b) {
    TILE_PTRS(CS_BIG); WARP_SETUP();
    uint32_t sXhi = sb + OFF_XHI, sXlo = sb + OFF_XLO;
    int b = blockIdx.x >> 6;
    int tile = blockIdx.x;

    if (tid < 128) { ctrl[tid] = f1b[tid]; ctrl[128 + tid] = f2b[tid]; }
    cpimg_h(sAhi, BIMG(tile & 63, 0), 0, tid); cpimg_h(sAlo, BIMG(tile & 63, 1), 0, tid);
    cpimg_h(sBhi, SCIMG(b, 0), 0, tid);        cpimg_h(sBlo, SCIMG(b, 1), 0, tid);
    CP_COMMIT();
    cpimg_h(sAhi, BIMG(tile & 63, 0), 1, tid); cpimg_h(sAlo, BIMG(tile & 63, 1), 1, tid);
    cpimg_h(sBhi, SCIMG(b, 0), 1, tid);        cpimg_h(sBlo, SCIMG(b, 1), 1, tid);
    cpimg(sXhi, HIMG(tile, 0), tid);           cpimg(sXlo, HIMG(tile, 1), tid);
    CP_COMMIT();

    float acc[2][4][4] = {};
    CP_WAIT1(); __syncthreads();
    gemm_h(sAhi, sAlo, sBhi, sBlo, acc, lane, m0, n0, 0);        // GEMM1.h0
    __syncthreads();
    cpimg_h(sBhi, WIMG(wbase, 0), 0, tid); cpimg_h(sBlo, WIMG(wbase, 1), 0, tid); CP_COMMIT();
    CP_WAIT1(); __syncthreads();
    gemm_h(sAhi, sAlo, sBhi, sBlo, acc, lane, m0, n0, 64);       // GEMM1.h1
    __syncthreads();
    cpimg_h(sBhi, WIMG(wbase, 0), 1, tid); cpimg_h(sBlo, WIMG(wbase, 1), 1, tid); CP_COMMIT();

    // ep1: xt = gelu(attn) + h -> A (next operand) and X (residual)
#pragma unroll
    for (int mt = 0; mt < 2; mt++)
#pragma unroll
        for (int j = 0; j < 4; j++) {
            int row = m0 + mt * 16 + qr, col = n0 + j * 8 + qc;
#pragma unroll
            for (int h = 0; h < 2; h++) {
                int r = row + h * 8;
                uint32_t a = taddr(r, col);
                float2 hh = unpack_split(*(uint32_t*)(Xhi + a), *(uint32_t*)(Xlo + a));
                float x0 = gelu_f(acc[mt][j][2*h])   + hh.x;
                float x1 = gelu_f(acc[mt][j][2*h+1]) + hh.y;
                uint32_t lw, hw = split_pack(x0, x1, lw);
                *(uint32_t*)(Ahi + a) = hw; *(uint32_t*)(Alo + a) = lw;
                *(uint32_t*)(Xhi + a) = hw; *(uint32_t*)(Xlo + a) = lw;
            }
        }

    float acc2[2][4][4] = {};
    CP_WAIT1(); __syncthreads();
    gemm_h(sAhi, sAlo, sBhi, sBlo, acc2, lane, m0, n0, 0);       // GEMM2.h0
    __syncthreads();
    cpimg_h(sBhi, WIMG(wbase + 1, 0), 0, tid); cpimg_h(sBlo, WIMG(wbase + 1, 1), 0, tid); CP_COMMIT();
    CP_WAIT1(); __syncthreads();
    gemm_h(sAhi, sAlo, sBhi, sBlo, acc2, lane, m0, n0, 64);      // GEMM2.h1
    __syncthreads();
    cpimg_h(sBhi, WIMG(wbase + 1, 0), 1, tid); cpimg_h(sBlo, WIMG(wbase + 1, 1), 1, tid); CP_COMMIT();

    // ep2: g = gelu(u + f1b) -> A
#pragma unroll
    for (int mt = 0; mt < 2; mt++)
#pragma unroll
        for (int j = 0; j < 4; j++) {
            int row = m0 + mt * 16 + qr, col = n0 + j * 8 + qc;
#pragma unroll
            for (int h = 0; h < 2; h++) {
                int r = row + h * 8;
                float g0 = gelu_f(acc2[mt][j][2*h]   + ctrl[col]);
                float g1 = gelu_f(acc2[mt][j][2*h+1] + ctrl[col + 1]);
                uint32_t lw, hw = split_pack(g0, g1, lw);
                uint32_t a = taddr(r, col);
                *(uint32_t*)(Ahi + a) = hw; *(uint32_t*)(Alo + a) = lw;
            }
        }

    float acc3[2][4][4] = {};
    CP_WAIT1(); __syncthreads();
    gemm_h(sAhi, sAlo, sBhi, sBlo, acc3, lane, m0, n0, 0);       // GEMM3.h0
    CP_WAIT0(); __syncthreads();
    gemm_h(sAhi, sAlo, sBhi, sBlo, acc3, lane, m0, n0, 64);      // GEMM3.h1

    char* oh = HIMG(tile, 0); char* ol = HIMG(tile, 1);
#pragma unroll
    for (int mt = 0; mt < 2; mt++)
#pragma unroll
        for (int j = 0; j < 4; j++) {
            int row = m0 + mt * 16 + qr, col = n0 + j * 8 + qc;
#pragma unroll
            for (int h = 0; h < 2; h++) {
                int r = row + h * 8;
                uint32_t a = taddr(r, col);
                float2 xt = unpack_split(*(uint32_t*)(Xhi + a), *(uint32_t*)(Xlo + a));
                store_split(oh, ol, r, col,
                            xt.x + acc3[mt][j][2*h]   + ctrl[128 + col],
                            xt.y + acc3[mt][j][2*h+1] + ctrl[128 + col + 1]);
            }
        }
}

// ---------------- gconv map (2 GEMMs, pipelined) -----------------------------
__global__ __launch_bounds__(NTH, 1)
void gconv_map_kernel(int widx, const float* __restrict__ wb, int act) {
    TILE_PTRS(CS_MID); WARP_SETUP();
    int b = blockIdx.x >> 6;
    int tile = blockIdx.x;

    if (tid < 128) ctrl[tid] = wb[tid];
    cpimg_h(sAhi, BIMG(tile & 63, 0), 0, tid); cpimg_h(sAlo, BIMG(tile & 63, 1), 0, tid);
    cpimg_h(sBhi, SCIMG(b, 0), 0, tid);        cpimg_h(sBlo, SCIMG(b, 1), 0, tid);
    CP_COMMIT();
    cpimg_h(sAhi, BIMG(tile & 63, 0), 1, tid); cpimg_h(sAlo, BIMG(tile & 63, 1), 1, tid);
    cpimg_h(sBhi, SCIMG(b, 0), 1, tid);        cpimg_h(sBlo, SCIMG(b, 1), 1, tid);
    CP_COMMIT();

    float acc[2][4][4] = {};
    CP_WAIT1(); __syncthreads();
    gemm_h(sAhi, sAlo, sBhi, sBlo, acc, lane, m0, n0, 0);        // GEMM1.h0
    __syncthreads();
    cpimg_h(sAhi, HIMG(tile, 0), 0, tid); cpimg_h(sAlo, HIMG(tile, 1), 0, tid);
    cpimg_h(sBhi, WIMG(widx, 0), 0, tid); cpimg_h(sBlo, WIMG(widx, 1), 0, tid);
    CP_COMMIT();
    CP_WAIT1(); __syncthreads();
    gemm_h(sAhi, sAlo, sBhi, sBlo, acc, lane, m0, n0, 64);       // GEMM1.h1
    __syncthreads();
    cpimg_h(sAhi, HIMG(tile, 0), 1, tid); cpimg_h(sAlo, HIMG(tile, 1), 1, tid);
    cpimg_h(sBhi, WIMG(widx, 0), 1, tid); cpimg_h(sBlo, WIMG(widx, 1), 1, tid);
    CP_COMMIT();
    CP_WAIT1(); __syncthreads();
    gemm_h(sAhi, sAlo, sBhi, sBlo, acc, lane, m0, n0, 0);        // GEMM2.h0
    CP_WAIT0(); __syncthreads();
    gemm_h(sAhi, sAlo, sBhi, sBlo, acc, lane, m0, n0, 64);       // GEMM2.h1
    __syncthreads();

    char* oh = HIMG(tile, 0); char* ol = HIMG(tile, 1);
#pragma unroll
    for (int mt = 0; mt < 2; mt++)
#pragma unroll
        for (int j = 0; j < 4; j++) {
            int row = m0 + mt * 16 + qr, col = n0 + j * 8 + qc;
#pragma unroll
            for (int h = 0; h < 2; h++) {
                int r = row + h * 8;
                uint32_t a = taddr(r, col);
                float2 hh = unpack_split(*(uint32_t*)(Ahi + a), *(uint32_t*)(Alo + a));
                float z0 = acc[mt][j][2*h]   + ctrl[col];
                float z1 = acc[mt][j][2*h+1] + ctrl[col + 1];
                if (act) { z0 = gelu_f(z0); z1 = gelu_f(z1); }
                store_split(oh, ol, r, col, hh.x + z0, hh.y + z1);
            }
        }
}

// ---------------- head --------------------------------------------------------
__global__ __launch_bounds__(NTH, 1)
void head_kernel(const float* __restrict__ fc1b, const float* __restrict__ fc2w,
                 const float* __restrict__ fc2b, float* __restrict__ out) {
    TILE_PTRS(CS_MID); WARP_SETUP();
    int tile = blockIdx.x;
    size_t tok0 = (size_t)tile * 128;
    int wn = wid >> 2;

    if (tid < 128) { ctrl[tid] = fc1b[tid]; ctrl[128 + tid] = fc2w[tid]; }
    float* partial = ctrl + 256;
    cpimg_h(sAhi, HIMG(tile, 0), 0, tid); cpimg_h(sAlo, HIMG(tile, 1), 0, tid);
    cpimg_h(sBhi, WIMG(7, 0), 0, tid);    cpimg_h(sBlo, WIMG(7, 1), 0, tid);
    CP_COMMIT();
    cpimg_h(sAhi, HIMG(tile, 0), 1, tid); cpimg_h(sAlo, HIMG(tile, 1), 1, tid);
    cpimg_h(sBhi, WIMG(7, 0), 1, tid);    cpimg_h(sBlo, WIMG(7, 1), 1, tid);
    CP_COMMIT();

    float acc[2][4][4] = {};
    CP_WAIT1(); __syncthreads();
    gemm_h(sAhi, sAlo, sBhi, sBlo, acc, lane, m0, n0, 0);
    CP_WAIT0(); __syncthreads();
    gemm_h(sAhi, sAlo, sBhi, sBlo, acc, lane, m0, n0, 64);

    float s[2][2] = {};
#pragma unroll
    for (int mt = 0; mt < 2; mt++)
#pragma unroll
        for (int j = 0; j < 4; j++) {
            int col = n0 + j * 8 + qc;
            s[mt][0] += gelu_f(acc[mt][j][0] + ctrl[col])     * ctrl[128 + col]
                      + gelu_f(acc[mt][j][1] + ctrl[col + 1]) * ctrl[128 + col + 1];
            s[mt][1] += gelu_f(acc[mt][j][2] + ctrl[col])     * ctrl[128 + col]
                      + gelu_f(acc[mt][j][3] + ctrl[col + 1]) * ctrl[128 + col + 1];
        }
#pragma unroll
    for (int mt = 0; mt < 2; mt++)
#pragma unroll
        for (int h = 0; h < 2; h++) {
            s[mt][h] += __shfl_xor_sync(0xffffffffu, s[mt][h], 1);
            s[mt][h] += __shfl_xor_sync(0xffffffffu, s[mt][h], 2);
        }
    if ((lane & 3) == 0) {
#pragma unroll
        for (int mt = 0; mt < 2; mt++) {
            partial[wn * 128 + m0 + mt * 16 + qr]     = s[mt][0];
            partial[wn * 128 + m0 + mt * 16 + qr + 8] = s[mt][1];
        }
    }
    __syncthreads();
    if (tid < 128)
        out[tok0 + tid] = partial[tid] + partial[128 + tid] + partial[256 + tid]
                        + partial[384 + tid] + fc2b[0];
}

// ---------------- launch ------------------------------------------------------
extern "C" void kernel_launch(void* const* d_in, const int* in_sizes, int n_in,
                              void* d_out, int out_size) {
    const float* x      = (const float*)d_in[0];
    const float* Bm     = (const float*)d_in[1];
    const float* fc0_w1 = (const float*)d_in[2];
    const float* fc0_b1 = (const float*)d_in[3];
    const float* fc0_w2 = (const float*)d_in[4];
    const float* fc0_b2 = (const float*)d_in[5];
    const float* a0_wk  = (const float*)d_in[6];
    const float* a0_bk  = (const float*)d_in[7];
    const float* a0_f1w = (const float*)d_in[8];
    const float* a0_f1b = (const float*)d_in[9];
    const float* a0_f2w = (const float*)d_in[10];
    const float* a0_f2b = (const float*)d_in[11];
    const float* c1_w   = (const float*)d_in[12];
    const float* w1_w   = (const float*)d_in[13];
    const float* w1_b   = (const float*)d_in[14];
    const float* a2_wk  = (const float*)d_in[15];
    const float* a2_bk  = (const float*)d_in[16];
    const float* a2_f1w = (const float*)d_in[17];
    const float* a2_f1b = (const float*)d_in[18];
    const float* a2_f2w = (const float*)d_in[19];
    const float* a2_f2b = (const float*)d_in[20];
    const float* c3_w   = (const float*)d_in[21];
    const float* w3_w   = (const float*)d_in[22];
    const float* w3_b   = (const float*)d_in[23];
    const float* fc1_w  = (const float*)d_in[24];
    const float* fc1_b  = (const float*)d_in[25];
    const float* fc2_w  = (const float*)d_in[26];
    const float* fc2_b  = (const float*)d_in[27];
    float* out = (float*)d_out;

    const int SM2 = (2 * D * AST + 1024) * sizeof(float);
    cudaFuncSetAttribute((const void*)fc0_kernel,       cudaFuncAttributeMaxDynamicSharedMemorySize, SM_MID);
    cudaFuncSetAttribute((const void*)reduce_kernel,    cudaFuncAttributeMaxDynamicSharedMemorySize, SM_MID);
    cudaFuncSetAttribute((const void*)attn_map_kernel,  cudaFuncAttributeMaxDynamicSharedMemorySize, SM_BIG);
    cudaFuncSetAttribute((const void*)gconv_map_kernel, cudaFuncAttributeMaxDynamicSharedMemorySize, SM_MID);
    cudaFuncSetAttribute((const void*)head_kernel,      cudaFuncAttributeMaxDynamicSharedMemorySize, SM_MID);
    cudaFuncSetAttribute((const void*)score_kernel,     cudaFuncAttributeMaxDynamicSharedMemorySize, SM2);

    colb_kernel<<<32, 128>>>(Bm);
    transpose_w_kernel<<<dim3(512, 4), dim3(32, 8)>>>(c1_w, 0);
    transpose_w_kernel<<<dim3(512, 4), dim3(32, 8)>>>(c3_w, 1);
    split_B_kernel<<<64, 256>>>(Bm);
    split_w_kernel<<<32, 256>>>(fc0_w2, 0);
    split_w_kernel<<<32, 256>>>(a0_f1w, 1);
    split_w_kernel<<<32, 256>>>(a0_f2w, 2);
    split_w_kernel<<<32, 256>>>(w1_w,   3);
    split_w_kernel<<<32, 256>>>(a2_f1w, 4);
    split_w_kernel<<<32, 256>>>(a2_f2w, 5);
    split_w_kernel<<<32, 256>>>(w3_w,   6);
    split_w_kernel<<<32, 256>>>(fc1_w,  7);

    fc0_kernel<<<NTILES, NTH, SM_MID>>>(x, fc0_w1, fc0_b1, fc0_b2);

    reduce_kernel<<<dim3(NCHUNK, BB), NTH, SM_MID>>>();
    reduce2_kernel<<<dim3(64, BB), 256>>>();
    score_kernel<<<BB, 256, SM2>>>(a0_wk, a0_bk);
    attn_map_kernel<<<NTILES, NTH, SM_BIG>>>(1, a0_f1b, a0_f2b);

    reduce_kernel<<<dim3(NCHUNK, BB), NTH, SM_MID>>>();
    reduce2_kernel<<<dim3(64, BB), 256>>>();
    gconv_modes_kernel<<<KM, 256>>>(0);
    gconv_map_kernel<<<NTILES, NTH, SM_MID>>>(3, w1_b, 1);

    reduce_kernel<<<dim3(NCHUNK, BB), NTH, SM_MID>>>();
    reduce2_kernel<<<dim3(64, BB), 256>>>();
    score_kernel<<<BB, 256, SM2>>>(a2_wk, a2_bk);
    attn_map_kernel<<<NTILES, NTH, SM_BIG>>>(4, a2_f1b, a2_f2b);

    reduce_kernel<<<dim3(NCHUNK, BB), NTH, SM_MID>>>();
    reduce2_kernel<<<dim3(64, BB), 256>>>();
    gconv_modes_kernel<<<KM, 256>>>(1);
    gconv_map_kernel<<<NTILES, NTH, SM_MID>>>(6, w3_b, 0);

    head_kernel<<<NTILES, NTH, SM_MID>>>(fc1_b, fc2_w, fc2_b, out);
}